// round 12
// baseline (speedup 1.0000x reference)
#include <cuda_runtime.h>
#include <math.h>

#define BB 64
#define NN 4096
#define DD 128
#define SS 7
#define HH 256
#define NW 64                    // warp-partials per batch
#define RPW 64                   // rows per flash block
#define EPSV 1e-8f

typedef unsigned long long u64;

// ---------------- f32x2 packed-fp32 helpers ----------------
__device__ __forceinline__ u64 fma2(u64 a, u64 b, u64 c) {
    u64 d; asm("fma.rn.f32x2 %0, %1, %2, %3;" : "=l"(d) : "l"(a), "l"(b), "l"(c)); return d;
}
__device__ __forceinline__ u64 mul2(u64 a, u64 b) {
    u64 d; asm("mul.rn.f32x2 %0, %1, %2;" : "=l"(d) : "l"(a), "l"(b)); return d;
}
__device__ __forceinline__ u64 add2(u64 a, u64 b) {
    u64 d; asm("add.rn.f32x2 %0, %1, %2;" : "=l"(d) : "l"(a), "l"(b)); return d;
}
__device__ __forceinline__ u64 dup2(float v) {
    u64 r; asm("mov.b64 %0, {%1, %1};" : "=l"(r) : "f"(v)); return r;
}
__device__ __forceinline__ float2 up2(u64 v) {
    float2 r; asm("mov.b64 {%0, %1}, %2;" : "=f"(r.x), "=f"(r.y) : "l"(v)); return r;
}
__device__ __forceinline__ float hadd2(u64 v) { float2 r = up2(v); return r.x + r.y; }

// ---------------- device scratch ----------------
__device__ __align__(16) float g_slots[BB * SS * DD];
__device__ __align__(16) float g_wq[BB * SS * DD];     // qt ∘ lin_g
__device__ float g_ws[BB * SS];                        // Σ (qt∘lin_g)
__device__ float g_c1[BB * SS];                        // qt · lin_b
__device__ __align__(16) float g_mv[BB * NN * 2];      // per-row (mean, rstd)
__device__ __align__(16) float g_es[BB * DD];          // per-batch Σ e_ln
__device__ __align__(16) float g_pesx[BB * NW * DD];
__device__ float g_pesm[BB * NW];
__device__ float g_pm[BB * NW * SS];
__device__ float g_pl[BB * NW * SS];
__device__ float g_pam[BB * NW * SS];
__device__ __align__(16) float g_pax[BB * NW * SS * DD];
// transposed weights: WT[in * O + out]
__device__ __align__(16) float g_WqT[DD * DD];
__device__ __align__(16) float g_WvT[DD * DD];
__device__ __align__(16) float g_WihT[DD * 3 * DD];
__device__ __align__(16) float g_WhhT[DD * 3 * DD];
__device__ __align__(16) float g_W1T[DD * HH];
__device__ __align__(16) float g_W2T[HH * DD];

// ---------------- fused: transpose all weights (blocks 0..191) + slot init
__global__ void k_trinit(const float* __restrict__ Wq, const float* __restrict__ Wv,
                         const float* __restrict__ Wih, const float* __restrict__ Whh,
                         const float* __restrict__ W1, const float* __restrict__ W2,
                         const float* __restrict__ noise, const float* __restrict__ mu,
                         const float* __restrict__ sg) {
    int id = blockIdx.x;
    if (id >= 192) {
        int i = (id - 192) * 256 + threadIdx.x;   // exactly BB*SS*DD = 224*256
        int dd = i & (DD - 1);
        g_slots[i] = fmaf(sg[dd], noise[i], mu[dd]);
        return;
    }
    const float* src; float* dst; int O, I, ti, to;
    if (id < 16)       { src = Wq;  dst = g_WqT;  O = DD;     I = DD; ti = id & 3; to = id >> 2; }
    else if (id < 32)  { id -= 16;  src = Wv;  dst = g_WvT;  O = DD;     I = DD; ti = id & 3; to = id >> 2; }
    else if (id < 80)  { id -= 32;  src = Wih; dst = g_WihT; O = 3 * DD; I = DD; ti = id & 3; to = id >> 2; }
    else if (id < 128) { id -= 80;  src = Whh; dst = g_WhhT; O = 3 * DD; I = DD; ti = id & 3; to = id >> 2; }
    else if (id < 160) { id -= 128; src = W1;  dst = g_W1T;  O = HH;     I = DD; ti = id & 3; to = id >> 2; }
    else               { id -= 160; src = W2;  dst = g_W2T;  O = DD;     I = HH; ti = id & 7; to = id >> 3; }
    __shared__ float tile[32][33];
    int tx = threadIdx.x & 31, ty = threadIdx.x >> 5;
    int i0 = ti * 32, o0 = to * 32;
#pragma unroll
    for (int k = 0; k < 32; k += 8)
        tile[ty + k][tx] = src[(o0 + ty + k) * I + i0 + tx];
    __syncthreads();
#pragma unroll
    for (int k = 0; k < 32; k += 8)
        dst[(i0 + ty + k) * O + o0 + tx] = tile[tx][ty + k];
}

// ---------------- prep: per-row LN stats + es partials (once) ------------
__global__ void __launch_bounds__(256) k_prep(const float* __restrict__ emb) {
    const int lane = threadIdx.x & 31, wid = threadIdx.x >> 5;
    const int b = blockIdx.y, w = blockIdx.x * 8 + wid;
    const float4* base = (const float4*)emb + (long long)(b * NN + w * RPW) * 32 + lane;
    float2* mvout = (float2*)g_mv + (b * NN + w * RPW);
    float4 esx = make_float4(0.f, 0.f, 0.f, 0.f);
    float esm = 0.f;
    for (int r = 0; r < RPW; r++) {
        float4 x = base[r * 32];
        float s1 = x.x + x.y + x.z + x.w;
        float s2 = fmaf(x.x, x.x, fmaf(x.y, x.y, fmaf(x.z, x.z, x.w * x.w)));
#pragma unroll
        for (int o = 16; o > 0; o >>= 1) {
            s1 += __shfl_xor_sync(~0u, s1, o);
            s2 += __shfl_xor_sync(~0u, s2, o);
        }
        float mean = s1 * (1.f / DD);
        float rstd = rsqrtf(fmaf(-mean, mean, s2 * (1.f / DD)) + 1e-5f);
        if (lane == 0) mvout[r] = make_float2(mean, rstd);
        esx.x = fmaf(rstd, x.x, esx.x);
        esx.y = fmaf(rstd, x.y, esx.y);
        esx.z = fmaf(rstd, x.z, esx.z);
        esx.w = fmaf(rstd, x.w, esx.w);
        esm = fmaf(rstd, mean, esm);
    }
    ((float4*)g_pesx)[(b * NW + w) * 32 + lane] = esx;
    if (lane == 0) g_pesm[b * NW + w] = esm;
}

// ---------------- es finalize ----------------
__global__ void k_es(const float* __restrict__ lg, const float* __restrict__ lb) {
    int b = blockIdx.x, d = threadIdx.x;
    float s0 = 0.f, s1 = 0.f, m0 = 0.f, m1 = 0.f;
#pragma unroll 8
    for (int w = 0; w < NW; w += 2) {
        s0 += g_pesx[(b * NW + w) * DD + d];
        s1 += g_pesx[(b * NW + w + 1) * DD + d];
        m0 += g_pesm[b * NW + w];
        m1 += g_pesm[b * NW + w + 1];
    }
    g_es[b * DD + d] = lg[d] * ((s0 + s1) - (m0 + m1)) + (float)NN * lb[d];
}

// ---------------- initial q projection (iter 0) --------------------------
__global__ void __launch_bounds__(128)
k_q0(const float* __restrict__ bq, const float* __restrict__ Wk,
     const float* __restrict__ lg, const float* __restrict__ lb,
     const float* __restrict__ ling, const float* __restrict__ linb) {
    const int bs = blockIdx.x;
    const int d = threadIdx.x;
    const int w = d >> 5, ln = d & 31;
    __shared__ float lnq[DD], sq[DD], red[8];

    float x = g_slots[bs * DD + d];
    float a = x, c = x * x;
#pragma unroll
    for (int o = 16; o > 0; o >>= 1) {
        a += __shfl_xor_sync(~0u, a, o);
        c += __shfl_xor_sync(~0u, c, o);
    }
    if (ln == 0) { red[w] = a; red[4 + w] = c; }
    __syncthreads();
    float mean = (red[0] + red[1] + red[2] + red[3]) * (1.f / DD);
    float msq = (red[4] + red[5] + red[6] + red[7]) * (1.f / DD);
    float rstd = rsqrtf(msq - mean * mean + 1e-5f);
    lnq[d] = fmaf((x - mean) * rstd, lg[d], lb[d]);
    __syncthreads();

    float q = bq[d];
#pragma unroll 8
    for (int e = 0; e < DD; e++) q = fmaf(lnq[e], g_WqT[e * DD + d], q);
    sq[d] = q;
    __syncthreads();
    float qt = 0.f;
#pragma unroll 8
    for (int e = 0; e < DD; e++) qt = fmaf(sq[e], Wk[e * DD + d], qt);

    float wqv = qt * ling[d];
    float c1v = qt * linb[d];
    g_wq[bs * DD + d] = wqv;
    float aa = wqv, cc = c1v;
#pragma unroll
    for (int o = 16; o > 0; o >>= 1) {
        aa += __shfl_xor_sync(~0u, aa, o);
        cc += __shfl_xor_sync(~0u, cc, o);
    }
    __syncthreads();
    if (ln == 0) { red[w] = aa; red[4 + w] = cc; }
    __syncthreads();
    if (d == 0) {
        g_ws[bs] = red[0] + red[1] + red[2] + red[3];
        g_c1[bs] = red[4] + red[5] + red[6] + red[7];
    }
}

// ---------------- flash: 2 warps share tile, s-split 4/3, f32x2 ----------
__global__ void __launch_bounds__(64)
k_flash(const float* __restrict__ emb) {
    __shared__ float4 xt[32][33];                 // 32 rows x 128 floats, padded
    __shared__ float4 wqs[SS][32];                // wq vectors
    __shared__ __align__(16) float ps[2][32][8];  // per-warp duplicated probs*rstd
    const int t = threadIdx.x;
    const int lane = t & 31, wid = t >> 5;
    const int b = blockIdx.y, wk = blockIdx.x;

    for (int idx = t; idx < SS * 32; idx += 64)
        ((float4*)wqs)[idx] = ((const float4*)g_wq)[b * SS * 32 + idx];

    const int s_lo = wid * 4;           // warp0: s 0..3, warp1: s 4..6
    const int ns = 4 - wid;
    float ws[4], c1[4];
#pragma unroll
    for (int si = 0; si < 4; si++) {
        int s = s_lo + si;
        ws[si] = (si < ns) ? g_ws[b * SS + s] : 0.f;
        c1[si] = (si < ns) ? g_c1[b * SS + s] : 0.f;
    }

    float m[4], lsum[4], amsum[4];
    u64 ac[4][2];
#pragma unroll
    for (int si = 0; si < 4; si++) {
        m[si] = -INFINITY; lsum[si] = 0.f; amsum[si] = 0.f;
        ac[si][0] = 0ull; ac[si][1] = 0ull;
    }
    const float4* gbase = (const float4*)emb + (long long)(b * NN + wk * RPW) * 32;
    const float2* mvb = (const float2*)g_mv + (b * NN + wk * RPW);
    __syncthreads();

    for (int t2 = 0; t2 < RPW / 32; t2++) {
        // stage 32 rows cooperatively (each warp 16 rows)
#pragma unroll 4
        for (int k = 0; k < 16; k++) {
            int row = wid * 16 + k;
            xt[row][lane] = gbase[(t2 * 32 + row) * 32 + lane];
        }
        float2 mv = mvb[t2 * 32 + lane];
        __syncthreads();

        // logits for own row (row = lane), own s-subset — f32x2
        u64 zp[4][2];
#pragma unroll
        for (int si = 0; si < 4; si++) { zp[si][0] = 0ull; zp[si][1] = 0ull; }
#pragma unroll 4
        for (int e = 0; e < 32; e++) {
            ulonglong2 xv = *(const ulonglong2*)&xt[lane][e];
#pragma unroll
            for (int si = 0; si < 4; si++) {
                if (si < ns) {
                    ulonglong2 wv = *(const ulonglong2*)&wqs[s_lo + si][e];
                    zp[si][0] = fma2(xv.x, wv.x, zp[si][0]);
                    zp[si][1] = fma2(xv.y, wv.y, zp[si][1]);
                }
            }
        }
        float z[4];
#pragma unroll
        for (int si = 0; si < 4; si++) {
            z[si] = hadd2(zp[si][0]) + hadd2(zp[si][1]);
            z[si] = fmaf(mv.y, fmaf(-mv.x, ws[si], z[si]), c1[si]);
        }

        // per-s warp max + rescale (warp-uniform branch)
#pragma unroll
        for (int si = 0; si < 4; si++) {
            if (si < ns) {
                float zm = z[si];
#pragma unroll
                for (int o = 16; o > 0; o >>= 1)
                    zm = fmaxf(zm, __shfl_xor_sync(~0u, zm, o));
                if (zm > m[si]) {
                    float sc = __expf(m[si] - zm);
                    m[si] = zm;
                    lsum[si] *= sc;
                    amsum[si] *= sc;
                    u64 sc2 = dup2(sc);
                    ac[si][0] = mul2(ac[si][0], sc2);
                    ac[si][1] = mul2(ac[si][1], sc2);
                }
            }
        }
        float pr[4];
#pragma unroll
        for (int si = 0; si < 4; si++) {
            float pv = __expf(z[si] - m[si]);
            if (si < ns) {
                lsum[si] += pv;
                pr[si] = pv * mv.y;
                amsum[si] = fmaf(pr[si], mv.x, amsum[si]);
            } else {
                pr[si] = 0.f;
            }
        }
        *(float4*)&ps[wid][lane][0] = make_float4(pr[0], pr[0], pr[1], pr[1]);
        *(float4*)&ps[wid][lane][4] = make_float4(pr[2], pr[2], pr[3], pr[3]);
        __syncthreads();

        // accumulate own s-subset over all 32 rows — f32x2
#pragma unroll 4
        for (int r = 0; r < 32; r++) {
            ulonglong2 xv = *(const ulonglong2*)&xt[r][lane];
            ulonglong2 pA = *(const ulonglong2*)&ps[wid][r][0];
            ulonglong2 pB = *(const ulonglong2*)&ps[wid][r][4];
            ac[0][0] = fma2(pA.x, xv.x, ac[0][0]);
            ac[0][1] = fma2(pA.x, xv.y, ac[0][1]);
            ac[1][0] = fma2(pA.y, xv.x, ac[1][0]);
            ac[1][1] = fma2(pA.y, xv.y, ac[1][1]);
            ac[2][0] = fma2(pB.x, xv.x, ac[2][0]);
            ac[2][1] = fma2(pB.x, xv.y, ac[2][1]);
            if (ns == 4) {
                ac[3][0] = fma2(pB.y, xv.x, ac[3][0]);
                ac[3][1] = fma2(pB.y, xv.y, ac[3][1]);
            }
        }
        __syncthreads();
    }

#pragma unroll
    for (int si = 0; si < 4; si++) {
        float a = lsum[si], c = amsum[si];
#pragma unroll
        for (int o = 16; o > 0; o >>= 1) {
            a += __shfl_xor_sync(~0u, a, o);
            c += __shfl_xor_sync(~0u, c, o);
        }
        lsum[si] = a; amsum[si] = c;
    }
    const int pidx = b * NW + wk;
#pragma unroll
    for (int si = 0; si < 4; si++) {
        if (si < ns) {
            ulonglong2 o2;
            o2.x = ac[si][0]; o2.y = ac[si][1];
            ((ulonglong2*)g_pax)[(pidx * SS + s_lo + si) * 32 + lane] = o2;
        }
    }
    if (lane == 0) {
#pragma unroll
        for (int si = 0; si < 4; si++) {
            if (si < ns) {
                g_pm[pidx * SS + s_lo + si] = m[si];
                g_pl[pidx * SS + s_lo + si] = lsum[si];
                g_pam[pidx * SS + s_lo + si] = amsum[si];
            }
        }
    }
}

// ---------------- k_up helpers ----------------
__device__ __forceinline__ float4 add4(float4 a, float4 b) {
    return make_float4(a.x + b.x, a.y + b.y, a.z + b.z, a.w + b.w);
}

// one e-sliced matmul pass (f32x2): part[es][s][dg] = Σ_{e in slice} in[s][e] * W4[e*rs4+off+dg]
template<int NE>
__device__ __forceinline__ void mm_pass(const float4* __restrict__ W4, int rs4, int off,
                                        const float* __restrict__ in, int instride,
                                        float* __restrict__ partf, int dg, int es) {
    u64 a[SS][2];
#pragma unroll
    for (int s = 0; s < SS; s++) { a[s][0] = 0ull; a[s][1] = 0ull; }
#pragma unroll 4
    for (int i = 0; i < NE; i++) {
        int e = es * NE + i;
        ulonglong2 wv = *(const ulonglong2*)&W4[e * rs4 + off + dg];
#pragma unroll
        for (int s = 0; s < SS; s++) {
            u64 v2 = dup2(in[s * instride + e]);
            a[s][0] = fma2(v2, wv.x, a[s][0]);
            a[s][1] = fma2(v2, wv.y, a[s][1]);
        }
    }
    ulonglong2* p2 = (ulonglong2*)partf;
#pragma unroll
    for (int s = 0; s < SS; s++) {
        ulonglong2 o2; o2.x = a[s][0]; o2.y = a[s][1];
        p2[(es * SS + s) * 32 + dg] = o2;
    }
}

__device__ __forceinline__ float4 red8(const float* __restrict__ partf, int s, int lane) {
    const ulonglong2* p2 = (const ulonglong2*)partf;
    ulonglong2 q = p2[(0 * SS + s) * 32 + lane];
    u64 r0 = q.x, r1 = q.y;
#pragma unroll
    for (int es = 1; es < 8; es++) {
        q = p2[(es * SS + s) * 32 + lane];
        r0 = add2(r0, q.x);
        r1 = add2(r1, q.y);
    }
    float2 lo = up2(r0), hi = up2(r1);
    return make_float4(lo.x, lo.y, hi.x, hi.y);
}

// ---------------- combine + GRU + FF + next-q: one block per batch -------
__global__ void __launch_bounds__(256)
k_up(const float* __restrict__ bvv,
     const float* __restrict__ bih, const float* __restrict__ bhh,
     const float* __restrict__ b1, const float* __restrict__ b2,
     const float* __restrict__ lfg, const float* __restrict__ lfb,
     const float* __restrict__ bq, const float* __restrict__ Wk,
     const float* __restrict__ lsg, const float* __restrict__ lsb,
     const float* __restrict__ ling, const float* __restrict__ linb,
     float* __restrict__ out, int last) {
    const int b = blockIdx.x;
    const int t = threadIdx.x;
    const int lane = t & 31, w = t >> 5;
    const int dg = lane, es = w;       // matmul-pass indexing (8 slices x 32 dgroups)
    const int s = w;                   // output phase: warp w owns slot s (w<7)
    const bool act = (t < 224);

    __shared__ __align__(16) float sm[10768];
    float* part = sm;                  // [8][7][32] float4 partials (7168 f)
    float* swm  = sm;                  // alias: merge weights sw[s][sp] (448 f, pre-B only)
    float* suv  = sm + 7168;           // su -> lnv -> lnq (896 f)
    float* sxv  = sm + 8064;           // updates x -> q (896 f)
    float* shf  = sm + 8960;           // shh (896) then sf[7][256] (1792 f)
    float* sLp  = sm + 10752;          // L per s
    float* sAMp = sm + 10759;          // AM per s

    // ---- A: merge flash partials (warp w handles slot s=w) ----
    if (w < 7) {
        float pm0 = g_pm[(b * NW + lane) * SS + s];
        float pm1 = g_pm[(b * NW + 32 + lane) * SS + s];
        float mx = fmaxf(pm0, pm1);
#pragma unroll
        for (int o = 16; o > 0; o >>= 1) mx = fmaxf(mx, __shfl_xor_sync(~0u, mx, o));
        float w0 = __expf(pm0 - mx), w1 = __expf(pm1 - mx);
        swm[s * 64 + lane] = w0;
        swm[s * 64 + 32 + lane] = w1;
        float pl0 = g_pl[(b * NW + lane) * SS + s], pl1 = g_pl[(b * NW + 32 + lane) * SS + s];
        float pa0 = g_pam[(b * NW + lane) * SS + s], pa1 = g_pam[(b * NW + 32 + lane) * SS + s];
        float lw = fmaf(pl0, w0, pl1 * w1);
        float aw = fmaf(pa0, w0, pa1 * w1);
#pragma unroll
        for (int o = 16; o > 0; o >>= 1) {
            lw += __shfl_xor_sync(~0u, lw, o);
            aw += __shfl_xor_sync(~0u, aw, o);
        }
        if (lane == 0) { sLp[s] = lw; sAMp[s] = aw; }
    }
    __syncthreads();

    // ---- AX: merged numerator -> u ; load h (f32x2) ----
    float4 hv = make_float4(0.f, 0.f, 0.f, 0.f);
    if (act) {
        u64 a00 = 0ull, a01 = 0ull, a10 = 0ull, a11 = 0ull;
        const ulonglong2* pax = (const ulonglong2*)g_pax + ((long long)(b * NW) * SS + s) * 32 + lane;
#pragma unroll 4
        for (int sp = 0; sp < NW; sp += 2) {
            u64 w02 = dup2(swm[s * 64 + sp]);
            u64 w12 = dup2(swm[s * 64 + sp + 1]);
            ulonglong2 p0 = pax[sp * (SS * 32)];
            ulonglong2 p1 = pax[(sp + 1) * (SS * 32)];
            a00 = fma2(p0.x, w02, a00); a01 = fma2(p0.y, w02, a01);
            a10 = fma2(p1.x, w12, a10); a11 = fma2(p1.y, w12, a11);
        }
        float2 axlo = up2(add2(a00, a10));
        float2 axhi = up2(add2(a01, a11));
        float4 ax = make_float4(axlo.x, axlo.y, axhi.x, axhi.y);
        float L = sLp[s], AM = sAMp[s];
        float invL = 1.f / L;
        const float invC = 1.f / (1.f + (float)NN * EPSV);
        float4 lg4 = ((const float4*)ling)[lane];
        float4 lb4 = ((const float4*)linb)[lane];
        float4 es4 = ((const float4*)g_es)[b * 32 + lane];
        float4 su4;
        su4.x = (lg4.x * (ax.x - AM) * invL + lb4.x + EPSV * es4.x) * invC;
        su4.y = (lg4.y * (ax.y - AM) * invL + lb4.y + EPSV * es4.y) * invC;
        su4.z = (lg4.z * (ax.z - AM) * invL + lb4.z + EPSV * es4.z) * invC;
        su4.w = (lg4.w * (ax.w - AM) * invL + lb4.w + EPSV * es4.w) * invC;
        *(float4*)&suv[s * DD + lane * 4] = su4;
        hv = ((const float4*)g_slots)[(b * SS + s) * 32 + lane];
        *(float4*)&shf[s * DD + lane * 4] = hv;
    }
    __syncthreads();

    // ---- B: updates = u @ Wv^T + bv ----
    mm_pass<16>((const float4*)g_WvT, 32, 0, suv, DD, part, dg, es);
    __syncthreads();
    if (act) {
        float4 x4 = add4(red8(part, s, lane), ((const float4*)bvv)[lane]);
        *(float4*)&sxv[s * DD + lane * 4] = x4;
    }
    __syncthreads();

    // ---- C: GRU, 6 e-sliced passes (gates in registers) ----
    float4 gir, giz, gin, ghr, ghz, ghn;
    mm_pass<16>((const float4*)g_WihT, 96, 0, sxv, DD, part, dg, es);
    __syncthreads();
    if (act) gir = add4(red8(part, s, lane), ((const float4*)bih)[lane]);
    __syncthreads();
    mm_pass<16>((const float4*)g_WihT, 96, 32, sxv, DD, part, dg, es);
    __syncthreads();
    if (act) giz = add4(red8(part, s, lane), ((const float4*)bih)[32 + lane]);
    __syncthreads();
    mm_pass<16>((const float4*)g_WihT, 96, 64, sxv, DD, part, dg, es);
    __syncthreads();
    if (act) gin = add4(red8(part, s, lane), ((const float4*)bih)[64 + lane]);
    __syncthreads();
    mm_pass<16>((const float4*)g_WhhT, 96, 0, shf, DD, part, dg, es);
    __syncthreads();
    if (act) ghr = add4(red8(part, s, lane), ((const float4*)bhh)[lane]);
    __syncthreads();
    mm_pass<16>((const float4*)g_WhhT, 96, 32, shf, DD, part, dg, es);
    __syncthreads();
    if (act) ghz = add4(red8(part, s, lane), ((const float4*)bhh)[32 + lane]);
    __syncthreads();
    mm_pass<16>((const float4*)g_WhhT, 96, 64, shf, DD, part, dg, es);
    __syncthreads();
    float4 sv = make_float4(0.f, 0.f, 0.f, 0.f);
    if (act) {
        ghn = add4(red8(part, s, lane), ((const float4*)bhh)[64 + lane]);
        float rr, zz, nn;
        rr = 1.f / (1.f + expf(-(gir.x + ghr.x)));
        zz = 1.f / (1.f + expf(-(giz.x + ghz.x)));
        nn = tanhf(fmaf(rr, ghn.x, gin.x));
        sv.x = fmaf(zz, hv.x - nn, nn);
        rr = 1.f / (1.f + expf(-(gir.y + ghr.y)));
        zz = 1.f / (1.f + expf(-(giz.y + ghz.y)));
        nn = tanhf(fmaf(rr, ghn.y, gin.y));
        sv.y = fmaf(zz, hv.y - nn, nn);
        rr = 1.f / (1.f + expf(-(gir.z + ghr.z)));
        zz = 1.f / (1.f + expf(-(giz.z + ghz.z)));
        nn = tanhf(fmaf(rr, ghn.z, gin.z));
        sv.z = fmaf(zz, hv.z - nn, nn);
        rr = 1.f / (1.f + expf(-(gir.w + ghr.w)));
        zz = 1.f / (1.f + expf(-(giz.w + ghz.w)));
        nn = tanhf(fmaf(rr, ghn.w, gin.w));
        sv.w = fmaf(zz, hv.w - nn, nn);
    }

    // ---- D: LN_ff (warp-per-slot reduce; warp 7 computes garbage, unused) ----
    {
        float a = sv.x + sv.y + sv.z + sv.w;
        float c = fmaf(sv.x, sv.x, fmaf(sv.y, sv.y, fmaf(sv.z, sv.z, sv.w * sv.w)));
#pragma unroll
        for (int o = 16; o > 0; o >>= 1) {
            a += __shfl_xor_sync(~0u, a, o);
            c += __shfl_xor_sync(~0u, c, o);
        }
        float mean = a * (1.f / DD);
        float rstd = rsqrtf(c * (1.f / DD) - mean * mean + 1e-5f);
        if (act) {
            float4 g4 = ((const float4*)lfg)[lane];
            float4 bb4 = ((const float4*)lfb)[lane];
            float4 lv;
            lv.x = fmaf((sv.x - mean) * rstd, g4.x, bb4.x);
            lv.y = fmaf((sv.y - mean) * rstd, g4.y, bb4.y);
            lv.z = fmaf((sv.z - mean) * rstd, g4.z, bb4.z);
            lv.w = fmaf((sv.w - mean) * rstd, g4.w, bb4.w);
            *(float4*)&suv[s * DD + lane * 4] = lv;   // lnv (su dead)
        }
    }
    __syncthreads();

    // ---- E: FF1 (relu), two output halves ----
    mm_pass<16>((const float4*)g_W1T, 64, 0, suv, DD, part, dg, es);
    __syncthreads();
    if (act) {
        float4 f = add4(red8(part, s, lane), ((const float4*)b1)[lane]);
        f.x = fmaxf(f.x, 0.f); f.y = fmaxf(f.y, 0.f);
        f.z = fmaxf(f.z, 0.f); f.w = fmaxf(f.w, 0.f);
        *(float4*)&shf[s * HH + lane * 4] = f;        // sf (shh dead)
    }
    __syncthreads();
    mm_pass<16>((const float4*)g_W1T, 64, 32, suv, DD, part, dg, es);
    __syncthreads();
    if (act) {
        float4 f = add4(red8(part, s, lane), ((const float4*)b1)[32 + lane]);
        f.x = fmaxf(f.x, 0.f); f.y = fmaxf(f.y, 0.f);
        f.z = fmaxf(f.z, 0.f); f.w = fmaxf(f.w, 0.f);
        *(float4*)&shf[s * HH + DD + lane * 4] = f;
    }
    __syncthreads();

    // ---- F: FF2 + residual ----
    mm_pass<32>((const float4*)g_W2T, 32, 0, shf, HH, part, dg, es);
    __syncthreads();
    float4 res = make_float4(0.f, 0.f, 0.f, 0.f);
    if (act) {
        float4 o2 = add4(red8(part, s, lane), ((const float4*)b2)[lane]);
        res.x = sv.x + o2.x; res.y = sv.y + o2.y;
        res.z = sv.z + o2.z; res.w = sv.w + o2.w;
        ((float4*)g_slots)[(b * SS + s) * 32 + lane] = res;
        if (last) ((float4*)out)[(b * SS + s) * 32 + lane] = res;
    }

    if (!last) {
        // ---- G1: LN_s (warp-per-slot reduce) ----
        {
            float a = res.x + res.y + res.z + res.w;
            float c = fmaf(res.x, res.x, fmaf(res.y, res.y, fmaf(res.z, res.z, res.w * res.w)));
#pragma unroll
            for (int o = 16; o > 0; o >>= 1) {
                a += __shfl_xor_sync(~0u, a, o);
                c += __shfl_xor_sync(~0u, c, o);
            }
            float mean = a * (1.f / DD);
            float rstd = rsqrtf(c * (1.f / DD) - mean * mean + 1e-5f);
            if (act) {
                float4 g4 = ((const float4*)lsg)[lane];
                float4 bb4 = ((const float4*)lsb)[lane];
                float4 lq;
                lq.x = fmaf((res.x - mean) * rstd, g4.x, bb4.x);
                lq.y = fmaf((res.y - mean) * rstd, g4.y, bb4.y);
                lq.z = fmaf((res.z - mean) * rstd, g4.z, bb4.z);
                lq.w = fmaf((res.w - mean) * rstd, g4.w, bb4.w);
                *(float4*)&suv[s * DD + lane * 4] = lq;    // lnq
            }
        }
        __syncthreads();
        // ---- G2: q = lnq @ WqT + bq ----
        mm_pass<16>((const float4*)g_WqT, 32, 0, suv, DD, part, dg, es);
        __syncthreads();
        if (act) {
            float4 q4 = add4(red8(part, s, lane), ((const float4*)bq)[lane]);
            *(float4*)&sxv[s * DD + lane * 4] = q4;
        }
        __syncthreads();
        // ---- G3: qt = q @ Wk  (Wk already e-major) ----
        mm_pass<16>((const float4*)Wk, 32, 0, sxv, DD, part, dg, es);
        __syncthreads();
        if (act) {
            float4 qt = red8(part, s, lane);
            float4 lg4 = ((const float4*)ling)[lane];
            float4 lb4 = ((const float4*)linb)[lane];
            float4 wq4;
            wq4.x = qt.x * lg4.x; wq4.y = qt.y * lg4.y;
            wq4.z = qt.z * lg4.z; wq4.w = qt.w * lg4.w;
            ((float4*)g_wq)[(b * SS + s) * 32 + lane] = wq4;
            float wss = wq4.x + wq4.y + wq4.z + wq4.w;
            float c1s = fmaf(qt.x, lb4.x, fmaf(qt.y, lb4.y,
                        fmaf(qt.z, lb4.z, qt.w * lb4.w)));
#pragma unroll
            for (int o = 16; o > 0; o >>= 1) {
                wss += __shfl_xor_sync(~0u, wss, o);
                c1s += __shfl_xor_sync(~0u, c1s, o);
            }
            if (lane == 0) { g_ws[b * SS + s] = wss; g_c1[b * SS + s] = c1s; }
        }
    }
}

// ---------------- launch ----------------
extern "C" void kernel_launch(void* const* d_in, const int* in_sizes, int n_in,
                              void* d_out, int out_size) {
    (void)in_sizes; (void)n_in; (void)out_size;
    const float* emb   = (const float*)d_in[0];
    const float* noise = (const float*)d_in[1];
    const float* mu    = (const float*)d_in[2];
    const float* sg    = (const float*)d_in[3];
    const float* Wk    = (const float*)d_in[4];
    /* bk = d_in[5] unused: constant per-(b,s) logit shift cancels in softmax */
    const float* Wq    = (const float*)d_in[6];
    const float* bq    = (const float*)d_in[7];
    const float* Wv    = (const float*)d_in[8];
    const float* bvv   = (const float*)d_in[9];
    const float* Wih   = (const float*)d_in[10];
    const float* Whh   = (const float*)d_in[11];
    const float* bih   = (const float*)d_in[12];
    const float* bhh   = (const float*)d_in[13];
    const float* W1    = (const float*)d_in[14];
    const float* b1    = (const float*)d_in[15];
    const float* W2    = (const float*)d_in[16];
    const float* b2    = (const float*)d_in[17];
    const float* lin_g = (const float*)d_in[18];
    const float* lin_b = (const float*)d_in[19];
    const float* ls_g  = (const float*)d_in[20];
    const float* ls_b  = (const float*)d_in[21];
    const float* lf_g  = (const float*)d_in[22];
    const float* lf_b  = (const float*)d_in[23];
    float* out = (float*)d_out;

    k_trinit<<<416, 256>>>(Wq, Wv, Wih, Whh, W1, W2, noise, mu, sg);   // #1
    k_prep<<<dim3(8, BB), 256>>>(emb);                                  // #2
    k_q0<<<BB * SS, DD>>>(bq, Wk, ls_g, ls_b, lin_g, lin_b);            // #3
    for (int it = 0; it < 3; it++) {
        k_flash<<<dim3(NW, BB), 64>>>(emb);                             // #4 on it==0
        if (it == 0) k_es<<<BB, DD>>>(lin_g, lin_b);                    // #5
        k_up<<<BB, 256>>>(bvv, bih, bhh, b1, b2, lf_g, lf_b,
                          bq, Wk, ls_g, ls_b, lin_g, lin_b, out, it == 2);
    }
}

// round 13
// speedup vs baseline: 1.3003x; 1.3003x over previous
#include <cuda_runtime.h>
#include <math.h>

#define BB 64
#define NN 4096
#define DD 128
#define SS 7
#define HH 256
#define NW 64                    // warp-partials per batch
#define RPW 64                   // rows per flash block
#define EPSV 1e-8f

// ---------------- device scratch ----------------
__device__ __align__(16) float g_slots[BB * SS * DD];
__device__ __align__(16) float g_wq[BB * SS * DD];     // qt ∘ lin_g
__device__ float g_ws[BB * SS];                        // Σ (qt∘lin_g)
__device__ float g_c1[BB * SS];                        // qt · lin_b
__device__ __align__(16) float g_mv[BB * NN * 2];      // per-row (mean, rstd)
__device__ __align__(16) float g_es[BB * DD];          // per-batch Σ e_ln
__device__ __align__(16) float g_pesx[BB * NW * DD];
__device__ float g_pesm[BB * NW];
__device__ float g_pm[BB * NW * SS];
__device__ float g_pl[BB * NW * SS];
__device__ float g_pam[BB * NW * SS];
__device__ __align__(16) float g_pax[BB * NW * SS * DD];
// transposed weights: WT[in * O + out]
__device__ __align__(16) float g_WqT[DD * DD];
__device__ __align__(16) float g_WvT[DD * DD];
__device__ __align__(16) float g_WihT[DD * 3 * DD];
__device__ __align__(16) float g_WhhT[DD * 3 * DD];
__device__ __align__(16) float g_W1T[DD * HH];
__device__ __align__(16) float g_W2T[HH * DD];

// ---------------- fused: transpose all weights (blocks 0..191) + slot init
__global__ void k_trinit(const float* __restrict__ Wq, const float* __restrict__ Wv,
                         const float* __restrict__ Wih, const float* __restrict__ Whh,
                         const float* __restrict__ W1, const float* __restrict__ W2,
                         const float* __restrict__ noise, const float* __restrict__ mu,
                         const float* __restrict__ sg) {
    int id = blockIdx.x;
    if (id >= 192) {
        int i = (id - 192) * 256 + threadIdx.x;   // exactly BB*SS*DD = 224*256
        int dd = i & (DD - 1);
        g_slots[i] = fmaf(sg[dd], noise[i], mu[dd]);
        return;
    }
    const float* src; float* dst; int O, I, ti, to;
    if (id < 16)       { src = Wq;  dst = g_WqT;  O = DD;     I = DD; ti = id & 3; to = id >> 2; }
    else if (id < 32)  { id -= 16;  src = Wv;  dst = g_WvT;  O = DD;     I = DD; ti = id & 3; to = id >> 2; }
    else if (id < 80)  { id -= 32;  src = Wih; dst = g_WihT; O = 3 * DD; I = DD; ti = id & 3; to = id >> 2; }
    else if (id < 128) { id -= 80;  src = Whh; dst = g_WhhT; O = 3 * DD; I = DD; ti = id & 3; to = id >> 2; }
    else if (id < 160) { id -= 128; src = W1;  dst = g_W1T;  O = HH;     I = DD; ti = id & 3; to = id >> 2; }
    else               { id -= 160; src = W2;  dst = g_W2T;  O = DD;     I = HH; ti = id & 7; to = id >> 3; }
    __shared__ float tile[32][33];
    int tx = threadIdx.x & 31, ty = threadIdx.x >> 5;
    int i0 = ti * 32, o0 = to * 32;
#pragma unroll
    for (int k = 0; k < 32; k += 8)
        tile[ty + k][tx] = src[(o0 + ty + k) * I + i0 + tx];
    __syncthreads();
#pragma unroll
    for (int k = 0; k < 32; k += 8)
        dst[(i0 + ty + k) * O + o0 + tx] = tile[tx][ty + k];
}

// ---------------- prep: per-row LN stats + es partials (once) ------------
__global__ void __launch_bounds__(256) k_prep(const float* __restrict__ emb) {
    const int lane = threadIdx.x & 31, wid = threadIdx.x >> 5;
    const int b = blockIdx.y, w = blockIdx.x * 8 + wid;
    const float4* base = (const float4*)emb + (long long)(b * NN + w * RPW) * 32 + lane;
    float2* mvout = (float2*)g_mv + (b * NN + w * RPW);
    float4 esx = make_float4(0.f, 0.f, 0.f, 0.f);
    float esm = 0.f;
    for (int r = 0; r < RPW; r++) {
        float4 x = base[r * 32];
        float s1 = x.x + x.y + x.z + x.w;
        float s2 = fmaf(x.x, x.x, fmaf(x.y, x.y, fmaf(x.z, x.z, x.w * x.w)));
#pragma unroll
        for (int o = 16; o > 0; o >>= 1) {
            s1 += __shfl_xor_sync(~0u, s1, o);
            s2 += __shfl_xor_sync(~0u, s2, o);
        }
        float mean = s1 * (1.f / DD);
        float rstd = rsqrtf(fmaf(-mean, mean, s2 * (1.f / DD)) + 1e-5f);
        if (lane == 0) mvout[r] = make_float2(mean, rstd);
        esx.x = fmaf(rstd, x.x, esx.x);
        esx.y = fmaf(rstd, x.y, esx.y);
        esx.z = fmaf(rstd, x.z, esx.z);
        esx.w = fmaf(rstd, x.w, esx.w);
        esm = fmaf(rstd, mean, esm);
    }
    ((float4*)g_pesx)[(b * NW + w) * 32 + lane] = esx;
    if (lane == 0) g_pesm[b * NW + w] = esm;
}

// ---------------- es finalize ----------------
__global__ void k_es(const float* __restrict__ lg, const float* __restrict__ lb) {
    int b = blockIdx.x, d = threadIdx.x;
    float s0 = 0.f, s1 = 0.f, m0 = 0.f, m1 = 0.f;
#pragma unroll 8
    for (int w = 0; w < NW; w += 2) {
        s0 += g_pesx[(b * NW + w) * DD + d];
        s1 += g_pesx[(b * NW + w + 1) * DD + d];
        m0 += g_pesm[b * NW + w];
        m1 += g_pesm[b * NW + w + 1];
    }
    g_es[b * DD + d] = lg[d] * ((s0 + s1) - (m0 + m1)) + (float)NN * lb[d];
}

// ---------------- initial q projection (iter 0) --------------------------
__global__ void __launch_bounds__(128)
k_q0(const float* __restrict__ bq, const float* __restrict__ Wk,
     const float* __restrict__ lg, const float* __restrict__ lb,
     const float* __restrict__ ling, const float* __restrict__ linb) {
    const int bs = blockIdx.x;
    const int d = threadIdx.x;
    const int w = d >> 5, ln = d & 31;
    __shared__ float lnq[DD], sq[DD], red[8];

    float x = g_slots[bs * DD + d];
    float a = x, c = x * x;
#pragma unroll
    for (int o = 16; o > 0; o >>= 1) {
        a += __shfl_xor_sync(~0u, a, o);
        c += __shfl_xor_sync(~0u, c, o);
    }
    if (ln == 0) { red[w] = a; red[4 + w] = c; }
    __syncthreads();
    float mean = (red[0] + red[1] + red[2] + red[3]) * (1.f / DD);
    float msq = (red[4] + red[5] + red[6] + red[7]) * (1.f / DD);
    float rstd = rsqrtf(msq - mean * mean + 1e-5f);
    lnq[d] = fmaf((x - mean) * rstd, lg[d], lb[d]);
    __syncthreads();

    float q = bq[d];
#pragma unroll 8
    for (int e = 0; e < DD; e++) q = fmaf(lnq[e], g_WqT[e * DD + d], q);
    sq[d] = q;
    __syncthreads();
    float qt = 0.f;
#pragma unroll 8
    for (int e = 0; e < DD; e++) qt = fmaf(sq[e], Wk[e * DD + d], qt);

    float wqv = qt * ling[d];
    float c1v = qt * linb[d];
    g_wq[bs * DD + d] = wqv;
    float aa = wqv, cc = c1v;
#pragma unroll
    for (int o = 16; o > 0; o >>= 1) {
        aa += __shfl_xor_sync(~0u, aa, o);
        cc += __shfl_xor_sync(~0u, cc, o);
    }
    __syncthreads();
    if (ln == 0) { red[w] = aa; red[4 + w] = cc; }
    __syncthreads();
    if (d == 0) {
        g_ws[bs] = red[0] + red[1] + red[2] + red[3];
        g_c1[bs] = red[4] + red[5] + red[6] + red[7];
    }
}

// ---------------- flash: single-warp, lane-per-row logits (R10 form) -----
__global__ void __launch_bounds__(32)
k_flash(const float* __restrict__ emb) {
    __shared__ float4 xt[32][33];       // 32 rows x 128 floats, padded
    __shared__ float4 wqs[SS][32];      // wq vectors
    __shared__ float ps[32][12];        // per-row probs*rstd (7 + pad)
    const int lane = threadIdx.x;
    const int b = blockIdx.y, w = blockIdx.x;

#pragma unroll
    for (int s = 0; s < SS; s++)
        wqs[s][lane] = ((const float4*)g_wq)[(b * SS + s) * 32 + lane];
    float ws[SS], c1[SS];
#pragma unroll
    for (int s = 0; s < SS; s++) {
        ws[s] = g_ws[b * SS + s];
        c1[s] = g_c1[b * SS + s];
    }

    float m[SS], lsum[SS], amsum[SS];
    float4 acc[SS];
#pragma unroll
    for (int s = 0; s < SS; s++) {
        m[s] = -INFINITY; lsum[s] = 0.f; amsum[s] = 0.f;
        acc[s] = make_float4(0.f, 0.f, 0.f, 0.f);
    }
    const float4* gbase = (const float4*)emb + (long long)(b * NN + w * RPW) * 32;
    const float2* mvb = (const float2*)g_mv + (b * NN + w * RPW);
    __syncwarp();

    for (int t2 = 0; t2 < RPW / 32; t2++) {
#pragma unroll 8
        for (int k = 0; k < 32; k++)
            xt[k][lane] = gbase[(t2 * 32 + k) * 32 + lane];
        float2 mv = mvb[t2 * 32 + lane];
        __syncwarp();

        float z[SS];
#pragma unroll
        for (int s = 0; s < SS; s++) z[s] = 0.f;
#pragma unroll 4
        for (int e = 0; e < 32; e++) {
            float4 xv = xt[lane][e];
#pragma unroll
            for (int s = 0; s < SS; s++) {
                float4 wv = wqs[s][e];
                z[s] = fmaf(xv.x, wv.x, fmaf(xv.y, wv.y,
                       fmaf(xv.z, wv.z, fmaf(xv.w, wv.w, z[s]))));
            }
        }
#pragma unroll
        for (int s = 0; s < SS; s++)
            z[s] = fmaf(mv.y, fmaf(-mv.x, ws[s], z[s]), c1[s]);

#pragma unroll
        for (int s = 0; s < SS; s++) {
            float zm = z[s];
#pragma unroll
            for (int o = 16; o > 0; o >>= 1)
                zm = fmaxf(zm, __shfl_xor_sync(~0u, zm, o));
            if (zm > m[s]) {
                float sc = __expf(m[s] - zm);
                m[s] = zm;
                lsum[s] *= sc;
                amsum[s] *= sc;
                acc[s].x *= sc; acc[s].y *= sc; acc[s].z *= sc; acc[s].w *= sc;
            }
        }
        float pr[SS];
#pragma unroll
        for (int s = 0; s < SS; s++) {
            float pv = __expf(z[s] - m[s]);
            lsum[s] += pv;
            pr[s] = pv * mv.y;
            amsum[s] = fmaf(pr[s], mv.x, amsum[s]);
        }
        *(float4*)&ps[lane][0] = make_float4(pr[0], pr[1], pr[2], pr[3]);
        *(float4*)&ps[lane][4] = make_float4(pr[4], pr[5], pr[6], 0.f);
        __syncwarp();

#pragma unroll 4
        for (int r = 0; r < 32; r++) {
            float4 xv = xt[r][lane];
            float4 pa = *(const float4*)&ps[r][0];
            float4 pb = *(const float4*)&ps[r][4];
            float prv[SS] = {pa.x, pa.y, pa.z, pa.w, pb.x, pb.y, pb.z};
#pragma unroll
            for (int s = 0; s < SS; s++) {
                acc[s].x = fmaf(prv[s], xv.x, acc[s].x);
                acc[s].y = fmaf(prv[s], xv.y, acc[s].y);
                acc[s].z = fmaf(prv[s], xv.z, acc[s].z);
                acc[s].w = fmaf(prv[s], xv.w, acc[s].w);
            }
        }
        __syncwarp();
    }

#pragma unroll
    for (int s = 0; s < SS; s++) {
        float a = lsum[s], c = amsum[s];
#pragma unroll
        for (int o = 16; o > 0; o >>= 1) {
            a += __shfl_xor_sync(~0u, a, o);
            c += __shfl_xor_sync(~0u, c, o);
        }
        lsum[s] = a; amsum[s] = c;
    }
    const int pidx = b * NW + w;
#pragma unroll
    for (int s = 0; s < SS; s++)
        ((float4*)g_pax)[(pidx * SS + s) * 32 + lane] = acc[s];
    if (lane == 0) {
#pragma unroll
        for (int s = 0; s < SS; s++) {
            g_pm[pidx * SS + s] = m[s];
            g_pl[pidx * SS + s] = lsum[s];
            g_pam[pidx * SS + s] = amsum[s];
        }
    }
}

// ---------------- k_up helpers ----------------
__device__ __forceinline__ float4 add4(float4 a, float4 b) {
    return make_float4(a.x + b.x, a.y + b.y, a.z + b.z, a.w + b.w);
}

// one e-sliced, s-split matmul pass:
// part[es][s0+si][dg] = Σ_{e in slice es} in[s0+si][e] * W4[e*rs4+off+dg]
template<int NE>
__device__ __forceinline__ void mm_pass(const float4* __restrict__ W4, int rs4, int off,
                                        const float* __restrict__ in, int instride,
                                        float* __restrict__ partf, int dg, int es,
                                        int s0, int ns) {
    float4 a[4];
#pragma unroll
    for (int si = 0; si < 4; si++) a[si] = make_float4(0.f, 0.f, 0.f, 0.f);
#pragma unroll 4
    for (int i = 0; i < NE; i++) {
        int e = es * NE + i;
        float4 wv = W4[e * rs4 + off + dg];
#pragma unroll
        for (int si = 0; si < 4; si++) {
            if (si < ns) {
                float v = in[(s0 + si) * instride + e];
                a[si].x = fmaf(v, wv.x, a[si].x);
                a[si].y = fmaf(v, wv.y, a[si].y);
                a[si].z = fmaf(v, wv.z, a[si].z);
                a[si].w = fmaf(v, wv.w, a[si].w);
            }
        }
    }
    float4* p4 = (float4*)partf;
#pragma unroll
    for (int si = 0; si < 4; si++)
        if (si < ns) p4[(es * SS + s0 + si) * 32 + dg] = a[si];
}

__device__ __forceinline__ float4 red8(const float* __restrict__ partf, int s, int lane) {
    const float4* p4 = (const float4*)partf;
    float4 r = p4[(0 * SS + s) * 32 + lane];
#pragma unroll
    for (int es = 1; es < 8; es++) {
        float4 q = p4[(es * SS + s) * 32 + lane];
        r.x += q.x; r.y += q.y; r.z += q.z; r.w += q.w;
    }
    return r;
}

// ---------------- combine + GRU + FF + next-q: one block per batch -------
// 512 threads = 16 warps: mm passes use (es = w&7) x (s-half = w>>3);
// output/reduce phases use warps 0..6 (warp w owns slot s=w).
__global__ void __launch_bounds__(512)
k_up(const float* __restrict__ bvv,
     const float* __restrict__ bih, const float* __restrict__ bhh,
     const float* __restrict__ b1, const float* __restrict__ b2,
     const float* __restrict__ lfg, const float* __restrict__ lfb,
     const float* __restrict__ bq, const float* __restrict__ Wk,
     const float* __restrict__ lsg, const float* __restrict__ lsb,
     const float* __restrict__ ling, const float* __restrict__ linb,
     float* __restrict__ out, int last) {
    const int b = blockIdx.x;
    const int t = threadIdx.x;
    const int lane = t & 31, w = t >> 5;    // 16 warps
    const int dg = lane;
    const int es = w & 7;                   // e-slice
    const int s0 = (w >> 3) * 4;            // s-half start: 0 or 4
    const int nsl = 4 - (w >> 3);           // 4 slots or 3
    const int s = w;                        // output phase: warp w owns slot s (w<7)
    const bool act = (w < 7);

    __shared__ __align__(16) float sm[10768];
    float* part = sm;                  // [8][7][32] float4 partials (7168 f)
    float* swm  = sm;                  // alias: merge weights sw[s][sp] (448 f, pre-B only)
    float* suv  = sm + 7168;           // su -> lnv -> lnq (896 f)
    float* sxv  = sm + 8064;           // updates x -> q (896 f)
    float* shf  = sm + 8960;           // shh (896) then sf[7][256] (1792 f)
    float* sLp  = sm + 10752;          // L per s
    float* sAMp = sm + 10759;          // AM per s

    // ---- A: merge flash partials (warp w handles slot s=w) ----
    if (act) {
        float pm0 = g_pm[(b * NW + lane) * SS + s];
        float pm1 = g_pm[(b * NW + 32 + lane) * SS + s];
        float mx = fmaxf(pm0, pm1);
#pragma unroll
        for (int o = 16; o > 0; o >>= 1) mx = fmaxf(mx, __shfl_xor_sync(~0u, mx, o));
        float w0 = __expf(pm0 - mx), w1 = __expf(pm1 - mx);
        swm[s * 64 + lane] = w0;
        swm[s * 64 + 32 + lane] = w1;
        float pl0 = g_pl[(b * NW + lane) * SS + s], pl1 = g_pl[(b * NW + 32 + lane) * SS + s];
        float pa0 = g_pam[(b * NW + lane) * SS + s], pa1 = g_pam[(b * NW + 32 + lane) * SS + s];
        float lw = fmaf(pl0, w0, pl1 * w1);
        float aw = fmaf(pa0, w0, pa1 * w1);
#pragma unroll
        for (int o = 16; o > 0; o >>= 1) {
            lw += __shfl_xor_sync(~0u, lw, o);
            aw += __shfl_xor_sync(~0u, aw, o);
        }
        if (lane == 0) { sLp[s] = lw; sAMp[s] = aw; }
    }
    __syncthreads();

    // ---- AX: merged numerator -> u ; load h ----
    float4 hv = make_float4(0.f, 0.f, 0.f, 0.f);
    if (act) {
        float4 a0 = make_float4(0.f, 0.f, 0.f, 0.f);
        float4 a1 = make_float4(0.f, 0.f, 0.f, 0.f);
        const float4* pax = (const float4*)g_pax + ((long long)(b * NW) * SS + s) * 32 + lane;
#pragma unroll 4
        for (int sp = 0; sp < NW; sp += 2) {
            float w0 = swm[s * 64 + sp], w1 = swm[s * 64 + sp + 1];
            float4 p0 = pax[sp * (SS * 32)];
            float4 p1 = pax[(sp + 1) * (SS * 32)];
            a0.x = fmaf(p0.x, w0, a0.x); a0.y = fmaf(p0.y, w0, a0.y);
            a0.z = fmaf(p0.z, w0, a0.z); a0.w = fmaf(p0.w, w0, a0.w);
            a1.x = fmaf(p1.x, w1, a1.x); a1.y = fmaf(p1.y, w1, a1.y);
            a1.z = fmaf(p1.z, w1, a1.z); a1.w = fmaf(p1.w, w1, a1.w);
        }
        float4 ax = add4(a0, a1);
        float L = sLp[s], AM = sAMp[s];
        float invL = 1.f / L;
        const float invC = 1.f / (1.f + (float)NN * EPSV);
        float4 lg4 = ((const float4*)ling)[lane];
        float4 lb4 = ((const float4*)linb)[lane];
        float4 es4 = ((const float4*)g_es)[b * 32 + lane];
        float4 su4;
        su4.x = (lg4.x * (ax.x - AM) * invL + lb4.x + EPSV * es4.x) * invC;
        su4.y = (lg4.y * (ax.y - AM) * invL + lb4.y + EPSV * es4.y) * invC;
        su4.z = (lg4.z * (ax.z - AM) * invL + lb4.z + EPSV * es4.z) * invC;
        su4.w = (lg4.w * (ax.w - AM) * invL + lb4.w + EPSV * es4.w) * invC;
        *(float4*)&suv[s * DD + lane * 4] = su4;
        hv = ((const float4*)g_slots)[(b * SS + s) * 32 + lane];
        *(float4*)&shf[s * DD + lane * 4] = hv;
    }
    __syncthreads();

    // ---- B: updates = u @ Wv^T + bv ----
    mm_pass<16>((const float4*)g_WvT, 32, 0, suv, DD, part, dg, es, s0, nsl);
    __syncthreads();
    if (act) {
        float4 x4 = add4(red8(part, s, lane), ((const float4*)bvv)[lane]);
        *(float4*)&sxv[s * DD + lane * 4] = x4;
    }
    __syncthreads();

    // ---- C: GRU, 6 e-sliced passes (gates in registers) ----
    float4 gir, giz, gin, ghr, ghz, ghn;
    mm_pass<16>((const float4*)g_WihT, 96, 0, sxv, DD, part, dg, es, s0, nsl);
    __syncthreads();
    if (act) gir = add4(red8(part, s, lane), ((const float4*)bih)[lane]);
    __syncthreads();
    mm_pass<16>((const float4*)g_WihT, 96, 32, sxv, DD, part, dg, es, s0, nsl);
    __syncthreads();
    if (act) giz = add4(red8(part, s, lane), ((const float4*)bih)[32 + lane]);
    __syncthreads();
    mm_pass<16>((const float4*)g_WihT, 96, 64, sxv, DD, part, dg, es, s0, nsl);
    __syncthreads();
    if (act) gin = add4(red8(part, s, lane), ((const float4*)bih)[64 + lane]);
    __syncthreads();
    mm_pass<16>((const float4*)g_WhhT, 96, 0, shf, DD, part, dg, es, s0, nsl);
    __syncthreads();
    if (act) ghr = add4(red8(part, s, lane), ((const float4*)bhh)[lane]);
    __syncthreads();
    mm_pass<16>((const float4*)g_WhhT, 96, 32, shf, DD, part, dg, es, s0, nsl);
    __syncthreads();
    if (act) ghz = add4(red8(part, s, lane), ((const float4*)bhh)[32 + lane]);
    __syncthreads();
    mm_pass<16>((const float4*)g_WhhT, 96, 64, shf, DD, part, dg, es, s0, nsl);
    __syncthreads();
    float4 sv = make_float4(0.f, 0.f, 0.f, 0.f);
    if (act) {
        ghn = add4(red8(part, s, lane), ((const float4*)bhh)[64 + lane]);
        float rr, zz, nn;
        rr = 1.f / (1.f + expf(-(gir.x + ghr.x)));
        zz = 1.f / (1.f + expf(-(giz.x + ghz.x)));
        nn = tanhf(fmaf(rr, ghn.x, gin.x));
        sv.x = fmaf(zz, hv.x - nn, nn);
        rr = 1.f / (1.f + expf(-(gir.y + ghr.y)));
        zz = 1.f / (1.f + expf(-(giz.y + ghz.y)));
        nn = tanhf(fmaf(rr, ghn.y, gin.y));
        sv.y = fmaf(zz, hv.y - nn, nn);
        rr = 1.f / (1.f + expf(-(gir.z + ghr.z)));
        zz = 1.f / (1.f + expf(-(giz.z + ghz.z)));
        nn = tanhf(fmaf(rr, ghn.z, gin.z));
        sv.z = fmaf(zz, hv.z - nn, nn);
        rr = 1.f / (1.f + expf(-(gir.w + ghr.w)));
        zz = 1.f / (1.f + expf(-(giz.w + ghz.w)));
        nn = tanhf(fmaf(rr, ghn.w, gin.w));
        sv.w = fmaf(zz, hv.w - nn, nn);
    }

    // ---- D: LN_ff (warp-per-slot reduce; warps >=7 compute garbage, unused) ----
    {
        float a = sv.x + sv.y + sv.z + sv.w;
        float c = fmaf(sv.x, sv.x, fmaf(sv.y, sv.y, fmaf(sv.z, sv.z, sv.w * sv.w)));
#pragma unroll
        for (int o = 16; o > 0; o >>= 1) {
            a += __shfl_xor_sync(~0u, a, o);
            c += __shfl_xor_sync(~0u, c, o);
        }
        float mean = a * (1.f / DD);
        float rstd = rsqrtf(c * (1.f / DD) - mean * mean + 1e-5f);
        if (act) {
            float4 g4 = ((const float4*)lfg)[lane];
            float4 bb4 = ((const float4*)lfb)[lane];
            float4 lv;
            lv.x = fmaf((sv.x - mean) * rstd, g4.x, bb4.x);
            lv.y = fmaf((sv.y - mean) * rstd, g4.y, bb4.y);
            lv.z = fmaf((sv.z - mean) * rstd, g4.z, bb4.z);
            lv.w = fmaf((sv.w - mean) * rstd, g4.w, bb4.w);
            *(float4*)&suv[s * DD + lane * 4] = lv;   // lnv (su dead)
        }
    }
    __syncthreads();

    // ---- E: FF1 (relu), two output halves ----
    mm_pass<16>((const float4*)g_W1T, 64, 0, suv, DD, part, dg, es, s0, nsl);
    __syncthreads();
    if (act) {
        float4 f = add4(red8(part, s, lane), ((const float4*)b1)[lane]);
        f.x = fmaxf(f.x, 0.f); f.y = fmaxf(f.y, 0.f);
        f.z = fmaxf(f.z, 0.f); f.w = fmaxf(f.w, 0.f);
        *(float4*)&shf[s * HH + lane * 4] = f;        // sf (shh dead)
    }
    __syncthreads();
    mm_pass<16>((const float4*)g_W1T, 64, 32, suv, DD, part, dg, es, s0, nsl);
    __syncthreads();
    if (act) {
        float4 f = add4(red8(part, s, lane), ((const float4*)b1)[32 + lane]);
        f.x = fmaxf(f.x, 0.f); f.y = fmaxf(f.y, 0.f);
        f.z = fmaxf(f.z, 0.f); f.w = fmaxf(f.w, 0.f);
        *(float4*)&shf[s * HH + DD + lane * 4] = f;
    }
    __syncthreads();

    // ---- F: FF2 + residual ----
    mm_pass<32>((const float4*)g_W2T, 32, 0, shf, HH, part, dg, es, s0, nsl);
    __syncthreads();
    float4 res = make_float4(0.f, 0.f, 0.f, 0.f);
    if (act) {
        float4 o2 = add4(red8(part, s, lane), ((const float4*)b2)[lane]);
        res.x = sv.x + o2.x; res.y = sv.y + o2.y;
        res.z = sv.z + o2.z; res.w = sv.w + o2.w;
        ((float4*)g_slots)[(b * SS + s) * 32 + lane] = res;
        if (last) ((float4*)out)[(b * SS + s) * 32 + lane] = res;
    }

    if (!last) {
        // ---- G1: LN_s (warp-per-slot reduce) ----
        {
            float a = res.x + res.y + res.z + res.w;
            float c = fmaf(res.x, res.x, fmaf(res.y, res.y, fmaf(res.z, res.z, res.w * res.w)));
#pragma unroll
            for (int o = 16; o > 0; o >>= 1) {
                a += __shfl_xor_sync(~0u, a, o);
                c += __shfl_xor_sync(~0u, c, o);
            }
            float mean = a * (1.f / DD);
            float rstd = rsqrtf(c * (1.f / DD) - mean * mean + 1e-5f);
            if (act) {
                float4 g4 = ((const float4*)lsg)[lane];
                float4 bb4 = ((const float4*)lsb)[lane];
                float4 lq;
                lq.x = fmaf((res.x - mean) * rstd, g4.x, bb4.x);
                lq.y = fmaf((res.y - mean) * rstd, g4.y, bb4.y);
                lq.z = fmaf((res.z - mean) * rstd, g4.z, bb4.z);
                lq.w = fmaf((res.w - mean) * rstd, g4.w, bb4.w);
                *(float4*)&suv[s * DD + lane * 4] = lq;    // lnq
            }
        }
        __syncthreads();
        // ---- G2: q = lnq @ WqT + bq ----
        mm_pass<16>((const float4*)g_WqT, 32, 0, suv, DD, part, dg, es, s0, nsl);
        __syncthreads();
        if (act) {
            float4 q4 = add4(red8(part, s, lane), ((const float4*)bq)[lane]);
            *(float4*)&sxv[s * DD + lane * 4] = q4;
        }
        __syncthreads();
        // ---- G3: qt = q @ Wk  (Wk already e-major) ----
        mm_pass<16>((const float4*)Wk, 32, 0, sxv, DD, part, dg, es, s0, nsl);
        __syncthreads();
        if (act) {
            float4 qt = red8(part, s, lane);
            float4 lg4 = ((const float4*)ling)[lane];
            float4 lb4 = ((const float4*)linb)[lane];
            float4 wq4;
            wq4.x = qt.x * lg4.x; wq4.y = qt.y * lg4.y;
            wq4.z = qt.z * lg4.z; wq4.w = qt.w * lg4.w;
            ((float4*)g_wq)[(b * SS + s) * 32 + lane] = wq4;
            float wss = wq4.x + wq4.y + wq4.z + wq4.w;
            float c1s = fmaf(qt.x, lb4.x, fmaf(qt.y, lb4.y,
                        fmaf(qt.z, lb4.z, qt.w * lb4.w)));
#pragma unroll
            for (int o = 16; o > 0; o >>= 1) {
                wss += __shfl_xor_sync(~0u, wss, o);
                c1s += __shfl_xor_sync(~0u, c1s, o);
            }
            if (lane == 0) { g_ws[b * SS + s] = wss; g_c1[b * SS + s] = c1s; }
        }
    }
}

// ---------------- launch ----------------
extern "C" void kernel_launch(void* const* d_in, const int* in_sizes, int n_in,
                              void* d_out, int out_size) {
    (void)in_sizes; (void)n_in; (void)out_size;
    const float* emb   = (const float*)d_in[0];
    const float* noise = (const float*)d_in[1];
    const float* mu    = (const float*)d_in[2];
    const float* sg    = (const float*)d_in[3];
    const float* Wk    = (const float*)d_in[4];
    /* bk = d_in[5] unused: constant per-(b,s) logit shift cancels in softmax */
    const float* Wq    = (const float*)d_in[6];
    const float* bq    = (const float*)d_in[7];
    const float* Wv    = (const float*)d_in[8];
    const float* bvv   = (const float*)d_in[9];
    const float* Wih   = (const float*)d_in[10];
    const float* Whh   = (const float*)d_in[11];
    const float* bih   = (const float*)d_in[12];
    const float* bhh   = (const float*)d_in[13];
    const float* W1    = (const float*)d_in[14];
    const float* b1    = (const float*)d_in[15];
    const float* W2    = (const float*)d_in[16];
    const float* b2    = (const float*)d_in[17];
    const float* lin_g = (const float*)d_in[18];
    const float* lin_b = (const float*)d_in[19];
    const float* ls_g  = (const float*)d_in[20];
    const float* ls_b  = (const float*)d_in[21];
    const float* lf_g  = (const float*)d_in[22];
    const float* lf_b  = (const float*)d_in[23];
    float* out = (float*)d_out;

    k_trinit<<<416, 256>>>(Wq, Wv, Wih, Whh, W1, W2, noise, mu, sg);   // #1
    k_prep<<<dim3(8, BB), 256>>>(emb);                                  // #2
    k_q0<<<BB * SS, DD>>>(bq, Wk, ls_g, ls_b, lin_g, lin_b);            // #3
    for (int it = 0; it < 3; it++) {
        k_flash<<<dim3(NW, BB), 32>>>(emb);                             // #4 on it==0
        if (it == 0) k_es<<<BB, DD>>>(lin_g, lin_b);                    // #5
        k_up<<<BB, 512>>>(bvv, bih, bhh, b1, b2, lf_g, lf_b,
                          bq, Wk, ls_g, ls_b, lin_g, lin_b, out, it == 2);
    }
}

// round 14
// speedup vs baseline: 1.3949x; 1.0728x over previous
#include <cuda_runtime.h>
#include <math.h>

#define BB 64
#define NN 4096
#define DD 128
#define SS 7
#define HH 256
#define NW 64                    // warp-partials per batch
#define RPW 64                   // rows per flash block
#define EPSV 1e-8f

// ---------------- device scratch ----------------
__device__ __align__(16) float g_slots[BB * SS * DD];
__device__ __align__(16) float g_wq[BB * SS * DD];     // qt ∘ lin_g
__device__ float g_ws[BB * SS];                        // Σ (qt∘lin_g)
__device__ float g_c1[BB * SS];                        // qt · lin_b
__device__ __align__(16) float g_mv[BB * NN * 2];      // per-row (mean, rstd)
__device__ __align__(16) float g_es[BB * DD];          // per-batch Σ e_ln
__device__ __align__(16) float g_pesx[BB * NW * DD];
__device__ float g_pesm[BB * NW];
__device__ float g_pm[BB * NW * SS];
__device__ float g_pl[BB * NW * SS];
__device__ float g_pam[BB * NW * SS];
__device__ __align__(16) float g_pax[BB * NW * SS * DD];
// transposed weights: WT[in * O + out]
__device__ __align__(16) float g_WqT[DD * DD];
__device__ __align__(16) float g_WvT[DD * DD];
__device__ __align__(16) float g_WihT[DD * 3 * DD];
__device__ __align__(16) float g_WhhT[DD * 3 * DD];
__device__ __align__(16) float g_W1T[DD * HH];
__device__ __align__(16) float g_W2T[HH * DD];

// ---------------- fused: transpose all weights (blocks 0..191) + slot init
__global__ void k_trinit(const float* __restrict__ Wq, const float* __restrict__ Wv,
                         const float* __restrict__ Wih, const float* __restrict__ Whh,
                         const float* __restrict__ W1, const float* __restrict__ W2,
                         const float* __restrict__ noise, const float* __restrict__ mu,
                         const float* __restrict__ sg) {
    int id = blockIdx.x;
    if (id >= 192) {
        int i = (id - 192) * 256 + threadIdx.x;   // exactly BB*SS*DD = 224*256
        int dd = i & (DD - 1);
        g_slots[i] = fmaf(sg[dd], noise[i], mu[dd]);
        return;
    }
    const float* src; float* dst; int O, I, ti, to;
    if (id < 16)       { src = Wq;  dst = g_WqT;  O = DD;     I = DD; ti = id & 3; to = id >> 2; }
    else if (id < 32)  { id -= 16;  src = Wv;  dst = g_WvT;  O = DD;     I = DD; ti = id & 3; to = id >> 2; }
    else if (id < 80)  { id -= 32;  src = Wih; dst = g_WihT; O = 3 * DD; I = DD; ti = id & 3; to = id >> 2; }
    else if (id < 128) { id -= 80;  src = Whh; dst = g_WhhT; O = 3 * DD; I = DD; ti = id & 3; to = id >> 2; }
    else if (id < 160) { id -= 128; src = W1;  dst = g_W1T;  O = HH;     I = DD; ti = id & 3; to = id >> 2; }
    else               { id -= 160; src = W2;  dst = g_W2T;  O = DD;     I = HH; ti = id & 7; to = id >> 3; }
    __shared__ float tile[32][33];
    int tx = threadIdx.x & 31, ty = threadIdx.x >> 5;
    int i0 = ti * 32, o0 = to * 32;
#pragma unroll
    for (int k = 0; k < 32; k += 8)
        tile[ty + k][tx] = src[(o0 + ty + k) * I + i0 + tx];
    __syncthreads();
#pragma unroll
    for (int k = 0; k < 32; k += 8)
        dst[(i0 + ty + k) * O + o0 + tx] = tile[tx][ty + k];
}

// ---------------- prep: per-row LN stats + es partials (once) ------------
__global__ void __launch_bounds__(256) k_prep(const float* __restrict__ emb) {
    const int lane = threadIdx.x & 31, wid = threadIdx.x >> 5;
    const int b = blockIdx.y, w = blockIdx.x * 8 + wid;
    const float4* base = (const float4*)emb + (long long)(b * NN + w * RPW) * 32 + lane;
    float2* mvout = (float2*)g_mv + (b * NN + w * RPW);
    float4 esx = make_float4(0.f, 0.f, 0.f, 0.f);
    float esm = 0.f;
    for (int r = 0; r < RPW; r++) {
        float4 x = base[r * 32];
        float s1 = x.x + x.y + x.z + x.w;
        float s2 = fmaf(x.x, x.x, fmaf(x.y, x.y, fmaf(x.z, x.z, x.w * x.w)));
#pragma unroll
        for (int o = 16; o > 0; o >>= 1) {
            s1 += __shfl_xor_sync(~0u, s1, o);
            s2 += __shfl_xor_sync(~0u, s2, o);
        }
        float mean = s1 * (1.f / DD);
        float rstd = rsqrtf(fmaf(-mean, mean, s2 * (1.f / DD)) + 1e-5f);
        if (lane == 0) mvout[r] = make_float2(mean, rstd);
        esx.x = fmaf(rstd, x.x, esx.x);
        esx.y = fmaf(rstd, x.y, esx.y);
        esx.z = fmaf(rstd, x.z, esx.z);
        esx.w = fmaf(rstd, x.w, esx.w);
        esm = fmaf(rstd, mean, esm);
    }
    ((float4*)g_pesx)[(b * NW + w) * 32 + lane] = esx;
    if (lane == 0) g_pesm[b * NW + w] = esm;
}

// ---------------- es finalize ----------------
__global__ void k_es(const float* __restrict__ lg, const float* __restrict__ lb) {
    int b = blockIdx.x, d = threadIdx.x;
    float s0 = 0.f, s1 = 0.f, m0 = 0.f, m1 = 0.f;
#pragma unroll 8
    for (int w = 0; w < NW; w += 2) {
        s0 += g_pesx[(b * NW + w) * DD + d];
        s1 += g_pesx[(b * NW + w + 1) * DD + d];
        m0 += g_pesm[b * NW + w];
        m1 += g_pesm[b * NW + w + 1];
    }
    g_es[b * DD + d] = lg[d] * ((s0 + s1) - (m0 + m1)) + (float)NN * lb[d];
}

// ---------------- initial q projection (iter 0) --------------------------
__global__ void __launch_bounds__(128)
k_q0(const float* __restrict__ bq, const float* __restrict__ Wk,
     const float* __restrict__ lg, const float* __restrict__ lb,
     const float* __restrict__ ling, const float* __restrict__ linb) {
    const int bs = blockIdx.x;
    const int d = threadIdx.x;
    const int w = d >> 5, ln = d & 31;
    __shared__ float lnq[DD], sq[DD], red[8];

    float x = g_slots[bs * DD + d];
    float a = x, c = x * x;
#pragma unroll
    for (int o = 16; o > 0; o >>= 1) {
        a += __shfl_xor_sync(~0u, a, o);
        c += __shfl_xor_sync(~0u, c, o);
    }
    if (ln == 0) { red[w] = a; red[4 + w] = c; }
    __syncthreads();
    float mean = (red[0] + red[1] + red[2] + red[3]) * (1.f / DD);
    float msq = (red[4] + red[5] + red[6] + red[7]) * (1.f / DD);
    float rstd = rsqrtf(msq - mean * mean + 1e-5f);
    lnq[d] = fmaf((x - mean) * rstd, lg[d], lb[d]);
    __syncthreads();

    float q = bq[d];
#pragma unroll 8
    for (int e = 0; e < DD; e++) q = fmaf(lnq[e], g_WqT[e * DD + d], q);
    sq[d] = q;
    __syncthreads();
    float qt = 0.f;
#pragma unroll 8
    for (int e = 0; e < DD; e++) qt = fmaf(sq[e], Wk[e * DD + d], qt);

    float wqv = qt * ling[d];
    float c1v = qt * linb[d];
    g_wq[bs * DD + d] = wqv;
    float aa = wqv, cc = c1v;
#pragma unroll
    for (int o = 16; o > 0; o >>= 1) {
        aa += __shfl_xor_sync(~0u, aa, o);
        cc += __shfl_xor_sync(~0u, cc, o);
    }
    __syncthreads();
    if (ln == 0) { red[w] = aa; red[4 + w] = cc; }
    __syncthreads();
    if (d == 0) {
        g_ws[bs] = red[0] + red[1] + red[2] + red[3];
        g_c1[bs] = red[4] + red[5] + red[6] + red[7];
    }
}

// ---------------- flash: single-warp, 16-row tiles (lower smem -> occ) ---
// lane pairs split each row's logit dot: rw = lane&15 (row), hf = lane>>4.
__global__ void __launch_bounds__(32)
k_flash(const float* __restrict__ emb) {
    __shared__ float4 xt[16][33];       // 16 rows x 128 floats, padded (8.4 KB)
    __shared__ float4 wqs[SS][32];      // wq vectors (3.5 KB)
    __shared__ __align__(16) float ps[16][8];  // per-row probs*rstd
    const int lane = threadIdx.x;
    const int rw = lane & 15, hf = lane >> 4;
    const int b = blockIdx.y, w = blockIdx.x;

#pragma unroll
    for (int s = 0; s < SS; s++)
        wqs[s][lane] = ((const float4*)g_wq)[(b * SS + s) * 32 + lane];
    float ws[SS], c1[SS];
#pragma unroll
    for (int s = 0; s < SS; s++) {
        ws[s] = g_ws[b * SS + s];
        c1[s] = g_c1[b * SS + s];
    }

    float m[SS], lsum[SS], amsum[SS];
    float4 acc[SS];
#pragma unroll
    for (int s = 0; s < SS; s++) {
        m[s] = -INFINITY; lsum[s] = 0.f; amsum[s] = 0.f;
        acc[s] = make_float4(0.f, 0.f, 0.f, 0.f);
    }
    const float4* gbase = (const float4*)emb + (long long)(b * NN + w * RPW) * 32;
    const float2* mvb = (const float2*)g_mv + (b * NN + w * RPW);
    __syncwarp();

    for (int t2 = 0; t2 < RPW / 16; t2++) {
        // stage 16 rows (coalesced)
#pragma unroll 8
        for (int k = 0; k < 16; k++)
            xt[k][lane] = gbase[(t2 * 16 + k) * 32 + lane];
        float2 mv = mvb[t2 * 16 + rw];
        __syncwarp();

        // logits: lane pair (rw, rw+16) splits the 128-dim dot in half
        float z[SS];
#pragma unroll
        for (int s = 0; s < SS; s++) z[s] = 0.f;
#pragma unroll 4
        for (int e = 0; e < 16; e++) {
            float4 xv = xt[rw][hf * 16 + e];
#pragma unroll
            for (int s = 0; s < SS; s++) {
                float4 wv = wqs[s][hf * 16 + e];
                z[s] = fmaf(xv.x, wv.x, fmaf(xv.y, wv.y,
                       fmaf(xv.z, wv.z, fmaf(xv.w, wv.w, z[s]))));
            }
        }
#pragma unroll
        for (int s = 0; s < SS; s++) {
            z[s] += __shfl_xor_sync(~0u, z[s], 16);   // combine halves
            z[s] = fmaf(mv.y, fmaf(-mv.x, ws[s], z[s]), c1[s]);
        }

        // tile max per s (rows duplicated across halves -> 4-step butterfly)
#pragma unroll
        for (int s = 0; s < SS; s++) {
            float zm = z[s];
#pragma unroll
            for (int o = 8; o > 0; o >>= 1)
                zm = fmaxf(zm, __shfl_xor_sync(~0u, zm, o));
            if (zm > m[s]) {                           // warp-uniform
                float sc = __expf(m[s] - zm);
                m[s] = zm;
                lsum[s] *= sc;
                amsum[s] *= sc;
                acc[s].x *= sc; acc[s].y *= sc; acc[s].z *= sc; acc[s].w *= sc;
            }
        }
        float pr[SS];
#pragma unroll
        for (int s = 0; s < SS; s++) {
            float pv = __expf(z[s] - m[s]);
            pr[s] = pv * mv.y;
            if (hf == 0) {                             // single-count per row
                lsum[s] += pv;
                amsum[s] = fmaf(pr[s], mv.x, amsum[s]);
            }
        }
        if (hf == 0) {
            *(float4*)&ps[rw][0] = make_float4(pr[0], pr[1], pr[2], pr[3]);
            *(float4*)&ps[rw][4] = make_float4(pr[4], pr[5], pr[6], 0.f);
        }
        __syncwarp();

        // accumulate: all 32 lanes own column chunks over 16 rows
#pragma unroll 4
        for (int r = 0; r < 16; r++) {
            float4 xv = xt[r][lane];
            float4 pa = *(const float4*)&ps[r][0];
            float4 pb = *(const float4*)&ps[r][4];
            float prv[SS] = {pa.x, pa.y, pa.z, pa.w, pb.x, pb.y, pb.z};
#pragma unroll
            for (int s = 0; s < SS; s++) {
                acc[s].x = fmaf(prv[s], xv.x, acc[s].x);
                acc[s].y = fmaf(prv[s], xv.y, acc[s].y);
                acc[s].z = fmaf(prv[s], xv.z, acc[s].z);
                acc[s].w = fmaf(prv[s], xv.w, acc[s].w);
            }
        }
        __syncwarp();
    }

    // reduce per-lane partials (hf==1 lanes hold zeros for lsum/amsum)
#pragma unroll
    for (int s = 0; s < SS; s++) {
        float a = lsum[s], c = amsum[s];
#pragma unroll
        for (int o = 16; o > 0; o >>= 1) {
            a += __shfl_xor_sync(~0u, a, o);
            c += __shfl_xor_sync(~0u, c, o);
        }
        lsum[s] = a; amsum[s] = c;
    }
    const int pidx = b * NW + w;
#pragma unroll
    for (int s = 0; s < SS; s++)
        ((float4*)g_pax)[(pidx * SS + s) * 32 + lane] = acc[s];
    if (lane == 0) {
#pragma unroll
        for (int s = 0; s < SS; s++) {
            g_pm[pidx * SS + s] = m[s];
            g_pl[pidx * SS + s] = lsum[s];
            g_pam[pidx * SS + s] = amsum[s];
        }
    }
}

// ---------------- k_up helpers ----------------
__device__ __forceinline__ float4 add4(float4 a, float4 b) {
    return make_float4(a.x + b.x, a.y + b.y, a.z + b.z, a.w + b.w);
}

// one e-sliced matmul pass: part[es][s][dg] = Σ_{e in slice} in[s][e] * W4[e*rs4+off+dg]
template<int NE>
__device__ __forceinline__ void mm_pass(const float4* __restrict__ W4, int rs4, int off,
                                        const float* __restrict__ in, int instride,
                                        float* __restrict__ partf, int dg, int es) {
    float4 a[SS];
#pragma unroll
    for (int s = 0; s < SS; s++) a[s] = make_float4(0.f, 0.f, 0.f, 0.f);
#pragma unroll 4
    for (int i = 0; i < NE; i++) {
        int e = es * NE + i;
        float4 wv = W4[e * rs4 + off + dg];
#pragma unroll
        for (int s = 0; s < SS; s++) {
            float v = in[s * instride + e];
            a[s].x = fmaf(v, wv.x, a[s].x);
            a[s].y = fmaf(v, wv.y, a[s].y);
            a[s].z = fmaf(v, wv.z, a[s].z);
            a[s].w = fmaf(v, wv.w, a[s].w);
        }
    }
    float4* p4 = (float4*)partf;
#pragma unroll
    for (int s = 0; s < SS; s++) p4[(es * SS + s) * 32 + dg] = a[s];
}

__device__ __forceinline__ float4 red8(const float* __restrict__ partf, int s, int lane) {
    const float4* p4 = (const float4*)partf;
    float4 r = p4[(0 * SS + s) * 32 + lane];
#pragma unroll
    for (int es = 1; es < 8; es++) {
        float4 q = p4[(es * SS + s) * 32 + lane];
        r.x += q.x; r.y += q.y; r.z += q.z; r.w += q.w;
    }
    return r;
}

// ---------------- combine + GRU + FF + next-q: one block per batch -------
__global__ void __launch_bounds__(256)
k_up(const float* __restrict__ bvv,
     const float* __restrict__ bih, const float* __restrict__ bhh,
     const float* __restrict__ b1, const float* __restrict__ b2,
     const float* __restrict__ lfg, const float* __restrict__ lfb,
     const float* __restrict__ bq, const float* __restrict__ Wk,
     const float* __restrict__ lsg, const float* __restrict__ lsb,
     const float* __restrict__ ling, const float* __restrict__ linb,
     float* __restrict__ out, int last) {
    const int b = blockIdx.x;
    const int t = threadIdx.x;
    const int lane = t & 31, w = t >> 5;
    const int dg = lane, es = w;       // matmul-pass indexing (8 slices x 32 dgroups)
    const int s = w;                   // output phase: warp w owns slot s (w<7)
    const bool act = (t < 224);

    __shared__ __align__(16) float sm[10768];
    float* part = sm;                  // [8][7][32] float4 partials (7168 f)
    float* swm  = sm;                  // alias: merge weights sw[s][sp] (448 f, pre-B only)
    float* suv  = sm + 7168;           // su -> lnv -> lnq (896 f)
    float* sxv  = sm + 8064;           // updates x -> q (896 f)
    float* shf  = sm + 8960;           // shh (896) then sf[7][256] (1792 f)
    float* sLp  = sm + 10752;          // L per s
    float* sAMp = sm + 10759;          // AM per s

    // ---- A: merge flash partials (warp w handles slot s=w) ----
    if (w < 7) {
        float pm0 = g_pm[(b * NW + lane) * SS + s];
        float pm1 = g_pm[(b * NW + 32 + lane) * SS + s];
        float mx = fmaxf(pm0, pm1);
#pragma unroll
        for (int o = 16; o > 0; o >>= 1) mx = fmaxf(mx, __shfl_xor_sync(~0u, mx, o));
        float w0 = __expf(pm0 - mx), w1 = __expf(pm1 - mx);
        swm[s * 64 + lane] = w0;
        swm[s * 64 + 32 + lane] = w1;
        float pl0 = g_pl[(b * NW + lane) * SS + s], pl1 = g_pl[(b * NW + 32 + lane) * SS + s];
        float pa0 = g_pam[(b * NW + lane) * SS + s], pa1 = g_pam[(b * NW + 32 + lane) * SS + s];
        float lw = fmaf(pl0, w0, pl1 * w1);
        float aw = fmaf(pa0, w0, pa1 * w1);
#pragma unroll
        for (int o = 16; o > 0; o >>= 1) {
            lw += __shfl_xor_sync(~0u, lw, o);
            aw += __shfl_xor_sync(~0u, aw, o);
        }
        if (lane == 0) { sLp[s] = lw; sAMp[s] = aw; }
    }
    __syncthreads();

    // ---- AX: merged numerator -> u ; load h ----
    float4 hv = make_float4(0.f, 0.f, 0.f, 0.f);
    if (act) {
        float4 a0 = make_float4(0.f, 0.f, 0.f, 0.f);
        float4 a1 = make_float4(0.f, 0.f, 0.f, 0.f);
        const float4* pax = (const float4*)g_pax + ((long long)(b * NW) * SS + s) * 32 + lane;
#pragma unroll 4
        for (int sp = 0; sp < NW; sp += 2) {
            float w0 = swm[s * 64 + sp], w1 = swm[s * 64 + sp + 1];
            float4 p0 = pax[sp * (SS * 32)];
            float4 p1 = pax[(sp + 1) * (SS * 32)];
            a0.x = fmaf(p0.x, w0, a0.x); a0.y = fmaf(p0.y, w0, a0.y);
            a0.z = fmaf(p0.z, w0, a0.z); a0.w = fmaf(p0.w, w0, a0.w);
            a1.x = fmaf(p1.x, w1, a1.x); a1.y = fmaf(p1.y, w1, a1.y);
            a1.z = fmaf(p1.z, w1, a1.z); a1.w = fmaf(p1.w, w1, a1.w);
        }
        float4 ax = add4(a0, a1);
        float L = sLp[s], AM = sAMp[s];
        float invL = 1.f / L;
        const float invC = 1.f / (1.f + (float)NN * EPSV);
        float4 lg4 = ((const float4*)ling)[lane];
        float4 lb4 = ((const float4*)linb)[lane];
        float4 es4 = ((const float4*)g_es)[b * 32 + lane];
        float4 su4;
        su4.x = (lg4.x * (ax.x - AM) * invL + lb4.x + EPSV * es4.x) * invC;
        su4.y = (lg4.y * (ax.y - AM) * invL + lb4.y + EPSV * es4.y) * invC;
        su4.z = (lg4.z * (ax.z - AM) * invL + lb4.z + EPSV * es4.z) * invC;
        su4.w = (lg4.w * (ax.w - AM) * invL + lb4.w + EPSV * es4.w) * invC;
        *(float4*)&suv[s * DD + lane * 4] = su4;
        hv = ((const float4*)g_slots)[(b * SS + s) * 32 + lane];
        *(float4*)&shf[s * DD + lane * 4] = hv;
    }
    __syncthreads();

    // ---- B: updates = u @ Wv^T + bv ----
    mm_pass<16>((const float4*)g_WvT, 32, 0, suv, DD, part, dg, es);
    __syncthreads();
    if (act) {
        float4 x4 = add4(red8(part, s, lane), ((const float4*)bvv)[lane]);
        *(float4*)&sxv[s * DD + lane * 4] = x4;
    }
    __syncthreads();

    // ---- C: GRU, 6 e-sliced passes (gates in registers) ----
    float4 gir, giz, gin, ghr, ghz, ghn;
    mm_pass<16>((const float4*)g_WihT, 96, 0, sxv, DD, part, dg, es);
    __syncthreads();
    if (act) gir = add4(red8(part, s, lane), ((const float4*)bih)[lane]);
    __syncthreads();
    mm_pass<16>((const float4*)g_WihT, 96, 32, sxv, DD, part, dg, es);
    __syncthreads();
    if (act) giz = add4(red8(part, s, lane), ((const float4*)bih)[32 + lane]);
    __syncthreads();
    mm_pass<16>((const float4*)g_WihT, 96, 64, sxv, DD, part, dg, es);
    __syncthreads();
    if (act) gin = add4(red8(part, s, lane), ((const float4*)bih)[64 + lane]);
    __syncthreads();
    mm_pass<16>((const float4*)g_WhhT, 96, 0, shf, DD, part, dg, es);
    __syncthreads();
    if (act) ghr = add4(red8(part, s, lane), ((const float4*)bhh)[lane]);
    __syncthreads();
    mm_pass<16>((const float4*)g_WhhT, 96, 32, shf, DD, part, dg, es);
    __syncthreads();
    if (act) ghz = add4(red8(part, s, lane), ((const float4*)bhh)[32 + lane]);
    __syncthreads();
    mm_pass<16>((const float4*)g_WhhT, 96, 64, shf, DD, part, dg, es);
    __syncthreads();
    float4 sv = make_float4(0.f, 0.f, 0.f, 0.f);
    if (act) {
        ghn = add4(red8(part, s, lane), ((const float4*)bhh)[64 + lane]);
        float rr, zz, nn;
        rr = 1.f / (1.f + expf(-(gir.x + ghr.x)));
        zz = 1.f / (1.f + expf(-(giz.x + ghz.x)));
        nn = tanhf(fmaf(rr, ghn.x, gin.x));
        sv.x = fmaf(zz, hv.x - nn, nn);
        rr = 1.f / (1.f + expf(-(gir.y + ghr.y)));
        zz = 1.f / (1.f + expf(-(giz.y + ghz.y)));
        nn = tanhf(fmaf(rr, ghn.y, gin.y));
        sv.y = fmaf(zz, hv.y - nn, nn);
        rr = 1.f / (1.f + expf(-(gir.z + ghr.z)));
        zz = 1.f / (1.f + expf(-(giz.z + ghz.z)));
        nn = tanhf(fmaf(rr, ghn.z, gin.z));
        sv.z = fmaf(zz, hv.z - nn, nn);
        rr = 1.f / (1.f + expf(-(gir.w + ghr.w)));
        zz = 1.f / (1.f + expf(-(giz.w + ghz.w)));
        nn = tanhf(fmaf(rr, ghn.w, gin.w));
        sv.w = fmaf(zz, hv.w - nn, nn);
    }

    // ---- D: LN_ff (warp-per-slot reduce; warp 7 computes garbage, unused) ----
    {
        float a = sv.x + sv.y + sv.z + sv.w;
        float c = fmaf(sv.x, sv.x, fmaf(sv.y, sv.y, fmaf(sv.z, sv.z, sv.w * sv.w)));
#pragma unroll
        for (int o = 16; o > 0; o >>= 1) {
            a += __shfl_xor_sync(~0u, a, o);
            c += __shfl_xor_sync(~0u, c, o);
        }
        float mean = a * (1.f / DD);
        float rstd = rsqrtf(c * (1.f / DD) - mean * mean + 1e-5f);
        if (act) {
            float4 g4 = ((const float4*)lfg)[lane];
            float4 bb4 = ((const float4*)lfb)[lane];
            float4 lv;
            lv.x = fmaf((sv.x - mean) * rstd, g4.x, bb4.x);
            lv.y = fmaf((sv.y - mean) * rstd, g4.y, bb4.y);
            lv.z = fmaf((sv.z - mean) * rstd, g4.z, bb4.z);
            lv.w = fmaf((sv.w - mean) * rstd, g4.w, bb4.w);
            *(float4*)&suv[s * DD + lane * 4] = lv;   // lnv (su dead)
        }
    }
    __syncthreads();

    // ---- E: FF1 (relu), two output halves ----
    mm_pass<16>((const float4*)g_W1T, 64, 0, suv, DD, part, dg, es);
    __syncthreads();
    if (act) {
        float4 f = add4(red8(part, s, lane), ((const float4*)b1)[lane]);
        f.x = fmaxf(f.x, 0.f); f.y = fmaxf(f.y, 0.f);
        f.z = fmaxf(f.z, 0.f); f.w = fmaxf(f.w, 0.f);
        *(float4*)&shf[s * HH + lane * 4] = f;        // sf (shh dead)
    }
    __syncthreads();
    mm_pass<16>((const float4*)g_W1T, 64, 32, suv, DD, part, dg, es);
    __syncthreads();
    if (act) {
        float4 f = add4(red8(part, s, lane), ((const float4*)b1)[32 + lane]);
        f.x = fmaxf(f.x, 0.f); f.y = fmaxf(f.y, 0.f);
        f.z = fmaxf(f.z, 0.f); f.w = fmaxf(f.w, 0.f);
        *(float4*)&shf[s * HH + DD + lane * 4] = f;
    }
    __syncthreads();

    // ---- F: FF2 + residual ----
    mm_pass<32>((const float4*)g_W2T, 32, 0, shf, HH, part, dg, es);
    __syncthreads();
    float4 res = make_float4(0.f, 0.f, 0.f, 0.f);
    if (act) {
        float4 o2 = add4(red8(part, s, lane), ((const float4*)b2)[lane]);
        res.x = sv.x + o2.x; res.y = sv.y + o2.y;
        res.z = sv.z + o2.z; res.w = sv.w + o2.w;
        ((float4*)g_slots)[(b * SS + s) * 32 + lane] = res;
        if (last) ((float4*)out)[(b * SS + s) * 32 + lane] = res;
    }

    if (!last) {
        // ---- G1: LN_s (warp-per-slot reduce) ----
        {
            float a = res.x + res.y + res.z + res.w;
            float c = fmaf(res.x, res.x, fmaf(res.y, res.y, fmaf(res.z, res.z, res.w * res.w)));
#pragma unroll
            for (int o = 16; o > 0; o >>= 1) {
                a += __shfl_xor_sync(~0u, a, o);
                c += __shfl_xor_sync(~0u, c, o);
            }
            float mean = a * (1.f / DD);
            float rstd = rsqrtf(c * (1.f / DD) - mean * mean + 1e-5f);
            if (act) {
                float4 g4 = ((const float4*)lsg)[lane];
                float4 bb4 = ((const float4*)lsb)[lane];
                float4 lq;
                lq.x = fmaf((res.x - mean) * rstd, g4.x, bb4.x);
                lq.y = fmaf((res.y - mean) * rstd, g4.y, bb4.y);
                lq.z = fmaf((res.z - mean) * rstd, g4.z, bb4.z);
                lq.w = fmaf((res.w - mean) * rstd, g4.w, bb4.w);
                *(float4*)&suv[s * DD + lane * 4] = lq;    // lnq
            }
        }
        __syncthreads();
        // ---- G2: q = lnq @ WqT + bq ----
        mm_pass<16>((const float4*)g_WqT, 32, 0, suv, DD, part, dg, es);
        __syncthreads();
        if (act) {
            float4 q4 = add4(red8(part, s, lane), ((const float4*)bq)[lane]);
            *(float4*)&sxv[s * DD + lane * 4] = q4;
        }
        __syncthreads();
        // ---- G3: qt = q @ Wk  (Wk already e-major) ----
        mm_pass<16>((const float4*)Wk, 32, 0, sxv, DD, part, dg, es);
        __syncthreads();
        if (act) {
            float4 qt = red8(part, s, lane);
            float4 lg4 = ((const float4*)ling)[lane];
            float4 lb4 = ((const float4*)linb)[lane];
            float4 wq4;
            wq4.x = qt.x * lg4.x; wq4.y = qt.y * lg4.y;
            wq4.z = qt.z * lg4.z; wq4.w = qt.w * lg4.w;
            ((float4*)g_wq)[(b * SS + s) * 32 + lane] = wq4;
            float wss = wq4.x + wq4.y + wq4.z + wq4.w;
            float c1s = fmaf(qt.x, lb4.x, fmaf(qt.y, lb4.y,
                        fmaf(qt.z, lb4.z, qt.w * lb4.w)));
#pragma unroll
            for (int o = 16; o > 0; o >>= 1) {
                wss += __shfl_xor_sync(~0u, wss, o);
                c1s += __shfl_xor_sync(~0u, c1s, o);
            }
            if (lane == 0) { g_ws[b * SS + s] = wss; g_c1[b * SS + s] = c1s; }
        }
    }
}

// ---------------- launch ----------------
extern "C" void kernel_launch(void* const* d_in, const int* in_sizes, int n_in,
                              void* d_out, int out_size) {
    (void)in_sizes; (void)n_in; (void)out_size;
    const float* emb   = (const float*)d_in[0];
    const float* noise = (const float*)d_in[1];
    const float* mu    = (const float*)d_in[2];
    const float* sg    = (const float*)d_in[3];
    const float* Wk    = (const float*)d_in[4];
    /* bk = d_in[5] unused: constant per-(b,s) logit shift cancels in softmax */
    const float* Wq    = (const float*)d_in[6];
    const float* bq    = (const float*)d_in[7];
    const float* Wv    = (const float*)d_in[8];
    const float* bvv   = (const float*)d_in[9];
    const float* Wih   = (const float*)d_in[10];
    const float* Whh   = (const float*)d_in[11];
    const float* bih   = (const float*)d_in[12];
    const float* bhh   = (const float*)d_in[13];
    const float* W1    = (const float*)d_in[14];
    const float* b1    = (const float*)d_in[15];
    const float* W2    = (const float*)d_in[16];
    const float* b2    = (const float*)d_in[17];
    const float* lin_g = (const float*)d_in[18];
    const float* lin_b = (const float*)d_in[19];
    const float* ls_g  = (const float*)d_in[20];
    const float* ls_b  = (const float*)d_in[21];
    const float* lf_g  = (const float*)d_in[22];
    const float* lf_b  = (const float*)d_in[23];
    float* out = (float*)d_out;

    k_trinit<<<416, 256>>>(Wq, Wv, Wih, Whh, W1, W2, noise, mu, sg);   // #1
    k_prep<<<dim3(8, BB), 256>>>(emb);                                  // #2
    k_q0<<<BB * SS, DD>>>(bq, Wk, ls_g, ls_b, lin_g, lin_b);            // #3
    for (int it = 0; it < 3; it++) {
        k_flash<<<dim3(NW, BB), 32>>>(emb);                             // #4 on it==0
        if (it == 0) k_es<<<BB, DD>>>(lin_g, lin_b);                    // #5
        k_up<<<BB, 256>>>(bvv, bih, bhh, b1, b2, lf_g, lf_b,
                          bq, Wk, ls_g, ls_b, lin_g, lin_b, out, it == 2);
    }
}

// round 16
// speedup vs baseline: 1.5312x; 1.0977x over previous
#include <cuda_runtime.h>
#include <math.h>

#define BB 64
#define NN 4096
#define DD 128
#define SS 7
#define HH 256
#define NW 64                    // warp-partials per batch
#define RPW 64                   // rows per flash block
#define EPSV 1e-8f

// ---------------- device scratch ----------------
__device__ __align__(16) float g_slots[BB * SS * DD];
__device__ __align__(16) float g_wq[BB * SS * DD];     // qt ∘ lin_g
__device__ float g_ws[BB * SS];                        // Σ (qt∘lin_g)
__device__ float g_c1[BB * SS];                        // qt · lin_b
__device__ __align__(16) float g_mv[BB * NN * 2];      // per-row (mean, rstd)
__device__ __align__(16) float g_es[BB * DD];          // per-batch Σ e_ln
__device__ __align__(16) float g_pesx[BB * NW * DD];
__device__ float g_pesm[BB * NW];
__device__ float g_pm[BB * NW * SS];
__device__ float g_pl[BB * NW * SS];
__device__ float g_pam[BB * NW * SS];
__device__ __align__(16) float g_pax[BB * NW * SS * DD];
// transposed weights: WT[in * O + out]
__device__ __align__(16) float g_WqT[DD * DD];
__device__ __align__(16) float g_WvT[DD * DD];
__device__ __align__(16) float g_WihT[DD * 3 * DD];
__device__ __align__(16) float g_WhhT[DD * 3 * DD];
__device__ __align__(16) float g_W1T[DD * HH];
__device__ __align__(16) float g_W2T[HH * DD];

// ---------------- cp.async helpers ----------------
__device__ __forceinline__ void cpa16(unsigned dst, const void* src) {
    asm volatile("cp.async.cg.shared.global [%0], [%1], 16;"
                 :: "r"(dst), "l"(src) : "memory");
}

// ---------------- fused: transpose all weights (blocks 0..191) + slot init
__global__ void k_trinit(const float* __restrict__ Wq, const float* __restrict__ Wv,
                         const float* __restrict__ Wih, const float* __restrict__ Whh,
                         const float* __restrict__ W1, const float* __restrict__ W2,
                         const float* __restrict__ noise, const float* __restrict__ mu,
                         const float* __restrict__ sg) {
    int id = blockIdx.x;
    if (id >= 192) {
        int i = (id - 192) * 256 + threadIdx.x;   // exactly BB*SS*DD = 224*256
        int dd = i & (DD - 1);
        g_slots[i] = fmaf(sg[dd], noise[i], mu[dd]);
        return;
    }
    const float* src; float* dst; int O, I, ti, to;
    if (id < 16)       { src = Wq;  dst = g_WqT;  O = DD;     I = DD; ti = id & 3; to = id >> 2; }
    else if (id < 32)  { id -= 16;  src = Wv;  dst = g_WvT;  O = DD;     I = DD; ti = id & 3; to = id >> 2; }
    else if (id < 80)  { id -= 32;  src = Wih; dst = g_WihT; O = 3 * DD; I = DD; ti = id & 3; to = id >> 2; }
    else if (id < 128) { id -= 80;  src = Whh; dst = g_WhhT; O = 3 * DD; I = DD; ti = id & 3; to = id >> 2; }
    else if (id < 160) { id -= 128; src = W1;  dst = g_W1T;  O = HH;     I = DD; ti = id & 3; to = id >> 2; }
    else               { id -= 160; src = W2;  dst = g_W2T;  O = DD;     I = HH; ti = id & 7; to = id >> 3; }
    __shared__ float tile[32][33];
    int tx = threadIdx.x & 31, ty = threadIdx.x >> 5;
    int i0 = ti * 32, o0 = to * 32;
#pragma unroll
    for (int k = 0; k < 32; k += 8)
        tile[ty + k][tx] = src[(o0 + ty + k) * I + i0 + tx];
    __syncthreads();
#pragma unroll
    for (int k = 0; k < 32; k += 8)
        dst[(i0 + ty + k) * O + o0 + tx] = tile[tx][ty + k];
}

// ---------------- prep: per-row LN stats + es partials (once) ------------
__global__ void __launch_bounds__(256) k_prep(const float* __restrict__ emb) {
    const int lane = threadIdx.x & 31, wid = threadIdx.x >> 5;
    const int b = blockIdx.y, w = blockIdx.x * 8 + wid;
    const float4* base = (const float4*)emb + (long long)(b * NN + w * RPW) * 32 + lane;
    float2* mvout = (float2*)g_mv + (b * NN + w * RPW);
    float4 esx = make_float4(0.f, 0.f, 0.f, 0.f);
    float esm = 0.f;
    for (int r = 0; r < RPW; r++) {
        float4 x = base[r * 32];
        float s1 = x.x + x.y + x.z + x.w;
        float s2 = fmaf(x.x, x.x, fmaf(x.y, x.y, fmaf(x.z, x.z, x.w * x.w)));
#pragma unroll
        for (int o = 16; o > 0; o >>= 1) {
            s1 += __shfl_xor_sync(~0u, s1, o);
            s2 += __shfl_xor_sync(~0u, s2, o);
        }
        float mean = s1 * (1.f / DD);
        float rstd = rsqrtf(fmaf(-mean, mean, s2 * (1.f / DD)) + 1e-5f);
        if (lane == 0) mvout[r] = make_float2(mean, rstd);
        esx.x = fmaf(rstd, x.x, esx.x);
        esx.y = fmaf(rstd, x.y, esx.y);
        esx.z = fmaf(rstd, x.z, esx.z);
        esx.w = fmaf(rstd, x.w, esx.w);
        esm = fmaf(rstd, mean, esm);
    }
    ((float4*)g_pesx)[(b * NW + w) * 32 + lane] = esx;
    if (lane == 0) g_pesm[b * NW + w] = esm;
}

// ---------------- es finalize ----------------
__global__ void k_es(const float* __restrict__ lg, const float* __restrict__ lb) {
    int b = blockIdx.x, d = threadIdx.x;
    float s0 = 0.f, s1 = 0.f, m0 = 0.f, m1 = 0.f;
#pragma unroll 8
    for (int w = 0; w < NW; w += 2) {
        s0 += g_pesx[(b * NW + w) * DD + d];
        s1 += g_pesx[(b * NW + w + 1) * DD + d];
        m0 += g_pesm[b * NW + w];
        m1 += g_pesm[b * NW + w + 1];
    }
    g_es[b * DD + d] = lg[d] * ((s0 + s1) - (m0 + m1)) + (float)NN * lb[d];
}

// ---------------- initial q projection (iter 0) --------------------------
__global__ void __launch_bounds__(128)
k_q0(const float* __restrict__ bq, const float* __restrict__ Wk,
     const float* __restrict__ lg, const float* __restrict__ lb,
     const float* __restrict__ ling, const float* __restrict__ linb) {
    const int bs = blockIdx.x;
    const int d = threadIdx.x;
    const int w = d >> 5, ln = d & 31;
    __shared__ float lnq[DD], sq[DD], red[8];

    float x = g_slots[bs * DD + d];
    float a = x, c = x * x;
#pragma unroll
    for (int o = 16; o > 0; o >>= 1) {
        a += __shfl_xor_sync(~0u, a, o);
        c += __shfl_xor_sync(~0u, c, o);
    }
    if (ln == 0) { red[w] = a; red[4 + w] = c; }
    __syncthreads();
    float mean = (red[0] + red[1] + red[2] + red[3]) * (1.f / DD);
    float msq = (red[4] + red[5] + red[6] + red[7]) * (1.f / DD);
    float rstd = rsqrtf(msq - mean * mean + 1e-5f);
    lnq[d] = fmaf((x - mean) * rstd, lg[d], lb[d]);
    __syncthreads();

    float q = bq[d];
#pragma unroll 8
    for (int e = 0; e < DD; e++) q = fmaf(lnq[e], g_WqT[e * DD + d], q);
    sq[d] = q;
    __syncthreads();
    float qt = 0.f;
#pragma unroll 8
    for (int e = 0; e < DD; e++) qt = fmaf(sq[e], Wk[e * DD + d], qt);

    float wqv = qt * ling[d];
    float c1v = qt * linb[d];
    g_wq[bs * DD + d] = wqv;
    float aa = wqv, cc = c1v;
#pragma unroll
    for (int o = 16; o > 0; o >>= 1) {
        aa += __shfl_xor_sync(~0u, aa, o);
        cc += __shfl_xor_sync(~0u, cc, o);
    }
    __syncthreads();
    if (ln == 0) { red[w] = aa; red[4 + w] = cc; }
    __syncthreads();
    if (d == 0) {
        g_ws[bs] = red[0] + red[1] + red[2] + red[3];
        g_c1[bs] = red[4] + red[5] + red[6] + red[7];
    }
}

// ---------------- flash: single-warp, cp.async double-buffered tiles -----
// lane pairs split each row's logit dot: rw = lane&15 (row), hf = lane>>4.
__global__ void __launch_bounds__(32)
k_flash(const float* __restrict__ emb) {
    __shared__ float4 xt[2][16][33];    // double-buffered 16-row tiles (16.9 KB)
    __shared__ float4 wqs[SS][32];      // wq vectors (3.5 KB)
    __shared__ __align__(16) float ps[16][8];  // per-row probs*rstd
    const int lane = threadIdx.x;
    const int rw = lane & 15, hf = lane >> 4;
    const int b = blockIdx.y, w = blockIdx.x;

#pragma unroll
    for (int s = 0; s < SS; s++)
        wqs[s][lane] = ((const float4*)g_wq)[(b * SS + s) * 32 + lane];
    float ws[SS], c1[SS];
#pragma unroll
    for (int s = 0; s < SS; s++) {
        ws[s] = g_ws[b * SS + s];
        c1[s] = g_c1[b * SS + s];
    }

    float m[SS], lsum[SS], amsum[SS];
    float4 acc[SS];
#pragma unroll
    for (int s = 0; s < SS; s++) {
        m[s] = -INFINITY; lsum[s] = 0.f; amsum[s] = 0.f;
        acc[s] = make_float4(0.f, 0.f, 0.f, 0.f);
    }
    const float4* gbase = (const float4*)emb + (long long)(b * NN + w * RPW) * 32;
    const float2* mvb = (const float2*)g_mv + (b * NN + w * RPW);
    const unsigned xtb = (unsigned)__cvta_generic_to_shared(&xt[0][0][0]);

    // preload all per-tile (mean,rstd) for this lane's row
    float2 mvp[4];
#pragma unroll
    for (int t2 = 0; t2 < 4; t2++) mvp[t2] = mvb[t2 * 16 + rw];

#define ISSUE_TILE(TT) do {                                             \
        const float4* _src = gbase + ((TT) * 16) * 32 + lane;           \
        unsigned _dst = xtb + (((TT) & 1) * 16 * 33 + lane) * 16;       \
        _Pragma("unroll")                                               \
        for (int _k = 0; _k < 16; _k++)                                 \
            cpa16(_dst + _k * 33 * 16, _src + _k * 32);                 \
        asm volatile("cp.async.commit_group;" ::: "memory");            \
    } while (0)

    ISSUE_TILE(0);

#pragma unroll
    for (int t2 = 0; t2 < 4; t2++) {
        if (t2 < 3) {
            ISSUE_TILE(t2 + 1);
            asm volatile("cp.async.wait_group 1;" ::: "memory");
        } else {
            asm volatile("cp.async.wait_group 0;" ::: "memory");
        }
        __syncwarp();
        const float4 (*xc)[33] = xt[t2 & 1];
        float2 mv = mvp[t2];

        // logits: lane pair (rw, rw+16) splits the 128-dim dot in half
        float z[SS];
#pragma unroll
        for (int s = 0; s < SS; s++) z[s] = 0.f;
#pragma unroll 4
        for (int e = 0; e < 16; e++) {
            float4 xv = xc[rw][hf * 16 + e];
#pragma unroll
            for (int s = 0; s < SS; s++) {
                float4 wv = wqs[s][hf * 16 + e];
                z[s] = fmaf(xv.x, wv.x, fmaf(xv.y, wv.y,
                       fmaf(xv.z, wv.z, fmaf(xv.w, wv.w, z[s]))));
            }
        }
#pragma unroll
        for (int s = 0; s < SS; s++) {
            z[s] += __shfl_xor_sync(~0u, z[s], 16);   // combine halves
            z[s] = fmaf(mv.y, fmaf(-mv.x, ws[s], z[s]), c1[s]);
        }

        // tile max per s (rows duplicated across halves -> 4-step butterfly)
#pragma unroll
        for (int s = 0; s < SS; s++) {
            float zm = z[s];
#pragma unroll
            for (int o = 8; o > 0; o >>= 1)
                zm = fmaxf(zm, __shfl_xor_sync(~0u, zm, o));
            if (zm > m[s]) {                           // warp-uniform
                float sc = __expf(m[s] - zm);
                m[s] = zm;
                lsum[s] *= sc;
                amsum[s] *= sc;
                acc[s].x *= sc; acc[s].y *= sc; acc[s].z *= sc; acc[s].w *= sc;
            }
        }
        float pr[SS];
#pragma unroll
        for (int s = 0; s < SS; s++) {
            float pv = __expf(z[s] - m[s]);
            pr[s] = pv * mv.y;
            if (hf == 0) {                             // single-count per row
                lsum[s] += pv;
                amsum[s] = fmaf(pr[s], mv.x, amsum[s]);
            }
        }
        if (hf == 0) {
            *(float4*)&ps[rw][0] = make_float4(pr[0], pr[1], pr[2], pr[3]);
            *(float4*)&ps[rw][4] = make_float4(pr[4], pr[5], pr[6], 0.f);
        }
        __syncwarp();

        // accumulate: all 32 lanes own column chunks over 16 rows
#pragma unroll 4
        for (int r = 0; r < 16; r++) {
            float4 xv = xc[r][lane];
            float4 pa = *(const float4*)&ps[r][0];
            float4 pb = *(const float4*)&ps[r][4];
            float prv[SS] = {pa.x, pa.y, pa.z, pa.w, pb.x, pb.y, pb.z};
#pragma unroll
            for (int s = 0; s < SS; s++) {
                acc[s].x = fmaf(prv[s], xv.x, acc[s].x);
                acc[s].y = fmaf(prv[s], xv.y, acc[s].y);
                acc[s].z = fmaf(prv[s], xv.z, acc[s].z);
                acc[s].w = fmaf(prv[s], xv.w, acc[s].w);
            }
        }
        __syncwarp();
    }
#undef ISSUE_TILE

    // reduce per-lane partials (hf==1 lanes hold zeros for lsum/amsum)
#pragma unroll
    for (int s = 0; s < SS; s++) {
        float a = lsum[s], c = amsum[s];
#pragma unroll
        for (int o = 16; o > 0; o >>= 1) {
            a += __shfl_xor_sync(~0u, a, o);
            c += __shfl_xor_sync(~0u, c, o);
        }
        lsum[s] = a; amsum[s] = c;
    }
    const int pidx = b * NW + w;
#pragma unroll
    for (int s = 0; s < SS; s++)
        ((float4*)g_pax)[(pidx * SS + s) * 32 + lane] = acc[s];
    if (lane == 0) {
#pragma unroll
        for (int s = 0; s < SS; s++) {
            g_pm[pidx * SS + s] = m[s];
            g_pl[pidx * SS + s] = lsum[s];
            g_pam[pidx * SS + s] = amsum[s];
        }
    }
}

// ---------------- k_up helpers ----------------
__device__ __forceinline__ float4 add4(float4 a, float4 b) {
    return make_float4(a.x + b.x, a.y + b.y, a.z + b.z, a.w + b.w);
}

// one e-sliced matmul pass: part[es][s][dg] = Σ_{e in slice} in[s][e] * W4[e*rs4+off+dg]
template<int NE>
__device__ __forceinline__ void mm_pass(const float4* __restrict__ W4, int rs4, int off,
                                        const float* __restrict__ in, int instride,
                                        float* __restrict__ partf, int dg, int es) {
    float4 a[SS];
#pragma unroll
    for (int s = 0; s < SS; s++) a[s] = make_float4(0.f, 0.f, 0.f, 0.f);
#pragma unroll 8
    for (int i = 0; i < NE; i++) {
        int e = es * NE + i;
        float4 wv = W4[e * rs4 + off + dg];
#pragma unroll
        for (int s = 0; s < SS; s++) {
            float v = in[s * instride + e];
            a[s].x = fmaf(v, wv.x, a[s].x);
            a[s].y = fmaf(v, wv.y, a[s].y);
            a[s].z = fmaf(v, wv.z, a[s].z);
            a[s].w = fmaf(v, wv.w, a[s].w);
        }
    }
    float4* p4 = (float4*)partf;
#pragma unroll
    for (int s = 0; s < SS; s++) p4[(es * SS + s) * 32 + dg] = a[s];
}

__device__ __forceinline__ float4 red8(const float* __restrict__ partf, int s, int lane) {
    const float4* p4 = (const float4*)partf;
    float4 r = p4[(0 * SS + s) * 32 + lane];
#pragma unroll
    for (int es = 1; es < 8; es++) {
        float4 q = p4[(es * SS + s) * 32 + lane];
        r.x += q.x; r.y += q.y; r.z += q.z; r.w += q.w;
    }
    return r;
}

// ---------------- combine + GRU + FF + next-q: one block per batch -------
__global__ void __launch_bounds__(256)
k_up(const float* __restrict__ bvv,
     const float* __restrict__ bih, const float* __restrict__ bhh,
     const float* __restrict__ b1, const float* __restrict__ b2,
     const float* __restrict__ lfg, const float* __restrict__ lfb,
     const float* __restrict__ bq, const float* __restrict__ Wk,
     const float* __restrict__ lsg, const float* __restrict__ lsb,
     const float* __restrict__ ling, const float* __restrict__ linb,
     float* __restrict__ out, int last) {
    const int b = blockIdx.x;
    const int t = threadIdx.x;
    const int lane = t & 31, w = t >> 5;
    const int dg = lane, es = w;       // matmul-pass indexing (8 slices x 32 dgroups)
    const int s = w;                   // output phase: warp w owns slot s (w<7)
    const bool act = (t < 224);

    __shared__ __align__(16) float sm[10768];
    float* part = sm;                  // [8][7][32] float4 partials (7168 f)
    float* swm  = sm;                  // alias: merge weights sw[s][sp] (448 f, pre-B only)
    float* suv  = sm + 7168;           // su -> lnv -> lnq (896 f)
    float* sxv  = sm + 8064;           // updates x -> q (896 f)
    float* shf  = sm + 8960;           // shh (896) then sf[7][256] (1792 f)
    float* sLp  = sm + 10752;          // L per s
    float* sAMp = sm + 10759;          // AM per s

    // ---- A: merge flash partials (warp w handles slot s=w) ----
    if (w < 7) {
        float pm0 = g_pm[(b * NW + lane) * SS + s];
        float pm1 = g_pm[(b * NW + 32 + lane) * SS + s];
        float mx = fmaxf(pm0, pm1);
#pragma unroll
        for (int o = 16; o > 0; o >>= 1) mx = fmaxf(mx, __shfl_xor_sync(~0u, mx, o));
        float w0 = __expf(pm0 - mx), w1 = __expf(pm1 - mx);
        swm[s * 64 + lane] = w0;
        swm[s * 64 + 32 + lane] = w1;
        float pl0 = g_pl[(b * NW + lane) * SS + s], pl1 = g_pl[(b * NW + 32 + lane) * SS + s];
        float pa0 = g_pam[(b * NW + lane) * SS + s], pa1 = g_pam[(b * NW + 32 + lane) * SS + s];
        float lw = fmaf(pl0, w0, pl1 * w1);
        float aw = fmaf(pa0, w0, pa1 * w1);
#pragma unroll
        for (int o = 16; o > 0; o >>= 1) {
            lw += __shfl_xor_sync(~0u, lw, o);
            aw += __shfl_xor_sync(~0u, aw, o);
        }
        if (lane == 0) { sLp[s] = lw; sAMp[s] = aw; }
    }
    __syncthreads();

    // ---- AX: merged numerator -> u ; load h ----
    float4 hv = make_float4(0.f, 0.f, 0.f, 0.f);
    if (act) {
        float4 a0 = make_float4(0.f, 0.f, 0.f, 0.f);
        float4 a1 = make_float4(0.f, 0.f, 0.f, 0.f);
        const float4* pax = (const float4*)g_pax + ((long long)(b * NW) * SS + s) * 32 + lane;
#pragma unroll 4
        for (int sp = 0; sp < NW; sp += 2) {
            float w0 = swm[s * 64 + sp], w1 = swm[s * 64 + sp + 1];
            float4 p0 = pax[sp * (SS * 32)];
            float4 p1 = pax[(sp + 1) * (SS * 32)];
            a0.x = fmaf(p0.x, w0, a0.x); a0.y = fmaf(p0.y, w0, a0.y);
            a0.z = fmaf(p0.z, w0, a0.z); a0.w = fmaf(p0.w, w0, a0.w);
            a1.x = fmaf(p1.x, w1, a1.x); a1.y = fmaf(p1.y, w1, a1.y);
            a1.z = fmaf(p1.z, w1, a1.z); a1.w = fmaf(p1.w, w1, a1.w);
        }
        float4 ax = add4(a0, a1);
        float L = sLp[s], AM = sAMp[s];
        float invL = 1.f / L;
        const float invC = 1.f / (1.f + (float)NN * EPSV);
        float4 lg4 = ((const float4*)ling)[lane];
        float4 lb4 = ((const float4*)linb)[lane];
        float4 es4 = ((const float4*)g_es)[b * 32 + lane];
        float4 su4;
        su4.x = (lg4.x * (ax.x - AM) * invL + lb4.x + EPSV * es4.x) * invC;
        su4.y = (lg4.y * (ax.y - AM) * invL + lb4.y + EPSV * es4.y) * invC;
        su4.z = (lg4.z * (ax.z - AM) * invL + lb4.z + EPSV * es4.z) * invC;
        su4.w = (lg4.w * (ax.w - AM) * invL + lb4.w + EPSV * es4.w) * invC;
        *(float4*)&suv[s * DD + lane * 4] = su4;
        hv = ((const float4*)g_slots)[(b * SS + s) * 32 + lane];
        *(float4*)&shf[s * DD + lane * 4] = hv;
    }
    __syncthreads();

    // ---- B: updates = u @ Wv^T + bv ----
    mm_pass<16>((const float4*)g_WvT, 32, 0, suv, DD, part, dg, es);
    __syncthreads();
    if (act) {
        float4 x4 = add4(red8(part, s, lane), ((const float4*)bvv)[lane]);
        *(float4*)&sxv[s * DD + lane * 4] = x4;
    }
    __syncthreads();

    // ---- C: GRU, 6 e-sliced passes (gates in registers) ----
    float4 gir, giz, gin, ghr, ghz, ghn;
    mm_pass<16>((const float4*)g_WihT, 96, 0, sxv, DD, part, dg, es);
    __syncthreads();
    if (act) gir = add4(red8(part, s, lane), ((const float4*)bih)[lane]);
    __syncthreads();
    mm_pass<16>((const float4*)g_WihT, 96, 32, sxv, DD, part, dg, es);
    __syncthreads();
    if (act) giz = add4(red8(part, s, lane), ((const float4*)bih)[32 + lane]);
    __syncthreads();
    mm_pass<16>((const float4*)g_WihT, 96, 64, sxv, DD, part, dg, es);
    __syncthreads();
    if (act) gin = add4(red8(part, s, lane), ((const float4*)bih)[64 + lane]);
    __syncthreads();
    mm_pass<16>((const float4*)g_WhhT, 96, 0, shf, DD, part, dg, es);
    __syncthreads();
    if (act) ghr = add4(red8(part, s, lane), ((const float4*)bhh)[lane]);
    __syncthreads();
    mm_pass<16>((const float4*)g_WhhT, 96, 32, shf, DD, part, dg, es);
    __syncthreads();
    if (act) ghz = add4(red8(part, s, lane), ((const float4*)bhh)[32 + lane]);
    __syncthreads();
    mm_pass<16>((const float4*)g_WhhT, 96, 64, shf, DD, part, dg, es);
    __syncthreads();
    float4 sv = make_float4(0.f, 0.f, 0.f, 0.f);
    if (act) {
        ghn = add4(red8(part, s, lane), ((const float4*)bhh)[64 + lane]);
        float rr, zz, nn;
        rr = 1.f / (1.f + expf(-(gir.x + ghr.x)));
        zz = 1.f / (1.f + expf(-(giz.x + ghz.x)));
        nn = tanhf(fmaf(rr, ghn.x, gin.x));
        sv.x = fmaf(zz, hv.x - nn, nn);
        rr = 1.f / (1.f + expf(-(gir.y + ghr.y)));
        zz = 1.f / (1.f + expf(-(giz.y + ghz.y)));
        nn = tanhf(fmaf(rr, ghn.y, gin.y));
        sv.y = fmaf(zz, hv.y - nn, nn);
        rr = 1.f / (1.f + expf(-(gir.z + ghr.z)));
        zz = 1.f / (1.f + expf(-(giz.z + ghz.z)));
        nn = tanhf(fmaf(rr, ghn.z, gin.z));
        sv.z = fmaf(zz, hv.z - nn, nn);
        rr = 1.f / (1.f + expf(-(gir.w + ghr.w)));
        zz = 1.f / (1.f + expf(-(giz.w + ghz.w)));
        nn = tanhf(fmaf(rr, ghn.w, gin.w));
        sv.w = fmaf(zz, hv.w - nn, nn);
    }

    // ---- D: LN_ff (warp-per-slot reduce; warp 7 computes garbage, unused) ----
    {
        float a = sv.x + sv.y + sv.z + sv.w;
        float c = fmaf(sv.x, sv.x, fmaf(sv.y, sv.y, fmaf(sv.z, sv.z, sv.w * sv.w)));
#pragma unroll
        for (int o = 16; o > 0; o >>= 1) {
            a += __shfl_xor_sync(~0u, a, o);
            c += __shfl_xor_sync(~0u, c, o);
        }
        float mean = a * (1.f / DD);
        float rstd = rsqrtf(c * (1.f / DD) - mean * mean + 1e-5f);
        if (act) {
            float4 g4 = ((const float4*)lfg)[lane];
            float4 bb4 = ((const float4*)lfb)[lane];
            float4 lv;
            lv.x = fmaf((sv.x - mean) * rstd, g4.x, bb4.x);
            lv.y = fmaf((sv.y - mean) * rstd, g4.y, bb4.y);
            lv.z = fmaf((sv.z - mean) * rstd, g4.z, bb4.z);
            lv.w = fmaf((sv.w - mean) * rstd, g4.w, bb4.w);
            *(float4*)&suv[s * DD + lane * 4] = lv;   // lnv (su dead)
        }
    }
    __syncthreads();

    // ---- E: FF1 (relu), two output halves ----
    mm_pass<16>((const float4*)g_W1T, 64, 0, suv, DD, part, dg, es);
    __syncthreads();
    if (act) {
        float4 f = add4(red8(part, s, lane), ((const float4*)b1)[lane]);
        f.x = fmaxf(f.x, 0.f); f.y = fmaxf(f.y, 0.f);
        f.z = fmaxf(f.z, 0.f); f.w = fmaxf(f.w, 0.f);
        *(float4*)&shf[s * HH + lane * 4] = f;        // sf (shh dead)
    }
    __syncthreads();
    mm_pass<16>((const float4*)g_W1T, 64, 32, suv, DD, part, dg, es);
    __syncthreads();
    if (act) {
        float4 f = add4(red8(part, s, lane), ((const float4*)b1)[32 + lane]);
        f.x = fmaxf(f.x, 0.f); f.y = fmaxf(f.y, 0.f);
        f.z = fmaxf(f.z, 0.f); f.w = fmaxf(f.w, 0.f);
        *(float4*)&shf[s * HH + DD + lane * 4] = f;
    }
    __syncthreads();

    // ---- F: FF2 + residual ----
    mm_pass<32>((const float4*)g_W2T, 32, 0, shf, HH, part, dg, es);
    __syncthreads();
    float4 res = make_float4(0.f, 0.f, 0.f, 0.f);
    if (act) {
        float4 o2 = add4(red8(part, s, lane), ((const float4*)b2)[lane]);
        res.x = sv.x + o2.x; res.y = sv.y + o2.y;
        res.z = sv.z + o2.z; res.w = sv.w + o2.w;
        ((float4*)g_slots)[(b * SS + s) * 32 + lane] = res;
        if (last) ((float4*)out)[(b * SS + s) * 32 + lane] = res;
    }

    if (!last) {
        // ---- G1: LN_s (warp-per-slot reduce) ----
        {
            float a = res.x + res.y + res.z + res.w;
            float c = fmaf(res.x, res.x, fmaf(res.y, res.y, fmaf(res.z, res.z, res.w * res.w)));
#pragma unroll
            for (int o = 16; o > 0; o >>= 1) {
                a += __shfl_xor_sync(~0u, a, o);
                c += __shfl_xor_sync(~0u, c, o);
            }
            float mean = a * (1.f / DD);
            float rstd = rsqrtf(c * (1.f / DD) - mean * mean + 1e-5f);
            if (act) {
                float4 g4 = ((const float4*)lsg)[lane];
                float4 bb4 = ((const float4*)lsb)[lane];
                float4 lq;
                lq.x = fmaf((res.x - mean) * rstd, g4.x, bb4.x);
                lq.y = fmaf((res.y - mean) * rstd, g4.y, bb4.y);
                lq.z = fmaf((res.z - mean) * rstd, g4.z, bb4.z);
                lq.w = fmaf((res.w - mean) * rstd, g4.w, bb4.w);
                *(float4*)&suv[s * DD + lane * 4] = lq;    // lnq
            }
        }
        __syncthreads();
        // ---- G2: q = lnq @ WqT + bq ----
        mm_pass<16>((const float4*)g_WqT, 32, 0, suv, DD, part, dg, es);
        __syncthreads();
        if (act) {
            float4 q4 = add4(red8(part, s, lane), ((const float4*)bq)[lane]);
            *(float4*)&sxv[s * DD + lane * 4] = q4;
        }
        __syncthreads();
        // ---- G3: qt = q @ Wk  (Wk already e-major) ----
        mm_pass<16>((const float4*)Wk, 32, 0, sxv, DD, part, dg, es);
        __syncthreads();
        if (act) {
            float4 qt = red8(part, s, lane);
            float4 lg4 = ((const float4*)ling)[lane];
            float4 lb4 = ((const float4*)linb)[lane];
            float4 wq4;
            wq4.x = qt.x * lg4.x; wq4.y = qt.y * lg4.y;
            wq4.z = qt.z * lg4.z; wq4.w = qt.w * lg4.w;
            ((float4*)g_wq)[(b * SS + s) * 32 + lane] = wq4;
            float wss = wq4.x + wq4.y + wq4.z + wq4.w;
            float c1s = fmaf(qt.x, lb4.x, fmaf(qt.y, lb4.y,
                        fmaf(qt.z, lb4.z, qt.w * lb4.w)));
#pragma unroll
            for (int o = 16; o > 0; o >>= 1) {
                wss += __shfl_xor_sync(~0u, wss, o);
                c1s += __shfl_xor_sync(~0u, c1s, o);
            }
            if (lane == 0) { g_ws[b * SS + s] = wss; g_c1[b * SS + s] = c1s; }
        }
    }
}

// ---------------- launch ----------------
extern "C" void kernel_launch(void* const* d_in, const int* in_sizes, int n_in,
                              void* d_out, int out_size) {
    (void)in_sizes; (void)n_in; (void)out_size;
    const float* emb   = (const float*)d_in[0];
    const float* noise = (const float*)d_in[1];
    const float* mu    = (const float*)d_in[2];
    const float* sg    = (const float*)d_in[3];
    const float* Wk    = (const float*)d_in[4];
    /* bk = d_in[5] unused: constant per-(b,s) logit shift cancels in softmax */
    const float* Wq    = (const float*)d_in[6];
    const float* bq    = (const float*)d_in[7];
    const float* Wv    = (const float*)d_in[8];
    const float* bvv   = (const float*)d_in[9];
    const float* Wih   = (const float*)d_in[10];
    const float* Whh   = (const float*)d_in[11];
    const float* bih   = (const float*)d_in[12];
    const float* bhh   = (const float*)d_in[13];
    const float* W1    = (const float*)d_in[14];
    const float* b1    = (const float*)d_in[15];
    const float* W2    = (const float*)d_in[16];
    const float* b2    = (const float*)d_in[17];
    const float* lin_g = (const float*)d_in[18];
    const float* lin_b = (const float*)d_in[19];
    const float* ls_g  = (const float*)d_in[20];
    const float* ls_b  = (const float*)d_in[21];
    const float* lf_g  = (const float*)d_in[22];
    const float* lf_b  = (const float*)d_in[23];
    float* out = (float*)d_out;

    k_trinit<<<416, 256>>>(Wq, Wv, Wih, Whh, W1, W2, noise, mu, sg);   // #1
    k_prep<<<dim3(8, BB), 256>>>(emb);                                  // #2
    k_q0<<<BB * SS, DD>>>(bq, Wk, ls_g, ls_b, lin_g, lin_b);            // #3
    for (int it = 0; it < 3; it++) {
        k_flash<<<dim3(NW, BB), 32>>>(emb);                             // #4 on it==0
        if (it == 0) k_es<<<BB, DD>>>(lin_g, lin_b);                    // #5
        k_up<<<BB, 256>>>(bvv, bih, bhh, b1, b2, lf_g, lf_b,
                          bq, Wk, ls_g, ls_b, lin_g, lin_b, out, it == 2);
    }
}